// round 3
// baseline (speedup 1.0000x reference)
#include <cuda_runtime.h>
#include <math.h>

#define B_  256
#define NV_ 35709
#define NR_ 107127          // NV*3
#define NF_ 70789
#define NK_ 68
#define CST 257             // coeff row stride

// output layout: [face_projection | face_color | landmarks | tri] all f32
#define OUT_COLOR ((size_t)B_ * NR_)
#define OUT_LM    ((size_t)2 * B_ * NR_)
#define OUT_TRI   (OUT_LM + (size_t)B_ * NK_ * 3)

typedef unsigned long long ull;

// -------- device scratch --------
__device__ float g_mean[3];
__device__ float g_rot[B_ * 9];
__device__ float g_coeffT[224 * B_];
__device__ float g_face_shape[(size_t)NR_ * B_];           // [row][b]
__device__ float g_tex[(size_t)NR_ * B_];                  // [row][b]
__device__ float g_face_norm[(size_t)(NF_ + 1) * 3 * B_];  // [face*3+d][b]
__device__ int   g_tri[NF_ * 3];
__device__ int   g_pbuf[NV_ * 8];
__device__ int   g_kp[NK_];

// ---------- f32x2 helpers ----------
__device__ __forceinline__ ull fma2(ull a, ull b, ull c) {
    ull d;
    asm("fma.rn.f32x2 %0, %1, %2, %3;" : "=l"(d) : "l"(a), "l"(b), "l"(c));
    return d;
}
__device__ __forceinline__ ull dup2(float x) {
    ull d;
    asm("mov.b64 %0, {%1, %1};" : "=l"(d) : "f"(x));
    return d;
}
__device__ __forceinline__ void unpack2(ull v, float& lo, float& hi) {
    asm("mov.b64 {%0, %1}, %2;" : "=f"(lo), "=f"(hi) : "l"(v));
}

// ============================================================
__global__ void k_idx(const void* __restrict__ tri,
                      const void* __restrict__ pbuf,
                      const void* __restrict__ kp)
{
    const int* t32 = (const int*)tri;
    bool is64 = true;
    #pragma unroll
    for (int i = 1; i < 32; i += 2) is64 = is64 && (t32[i] == 0);

    int gid = blockIdx.x * blockDim.x + threadIdx.x;
    int stride = gridDim.x * blockDim.x;
    if (is64) {
        const long long* a = (const long long*)tri;
        for (int i = gid; i < NF_ * 3; i += stride) g_tri[i] = (int)a[i];
        const long long* b = (const long long*)pbuf;
        for (int i = gid; i < NV_ * 8; i += stride) g_pbuf[i] = (int)b[i];
        const long long* c = (const long long*)kp;
        for (int i = gid; i < NK_; i += stride) g_kp[i] = (int)c[i];
    } else {
        const int* a = (const int*)tri;
        for (int i = gid; i < NF_ * 3; i += stride) g_tri[i] = a[i];
        const int* b = (const int*)pbuf;
        for (int i = gid; i < NV_ * 8; i += stride) g_pbuf[i] = b[i];
        const int* c = (const int*)kp;
        for (int i = gid; i < NK_; i += stride) g_kp[i] = c[i];
    }
}

// ============================================================
__global__ void k_prep(const float* __restrict__ coeff,
                       const float* __restrict__ meanshape)
{
    __shared__ float rx[256], ry[256], rz[256];
    int t = threadIdx.x;
    float s0 = 0.f, s1 = 0.f, s2 = 0.f;
    for (int v = t; v < NV_; v += 256) {
        s0 += meanshape[v * 3 + 0];
        s1 += meanshape[v * 3 + 1];
        s2 += meanshape[v * 3 + 2];
    }
    rx[t] = s0; ry[t] = s1; rz[t] = s2;
    __syncthreads();
    for (int off = 128; off > 0; off >>= 1) {
        if (t < off) { rx[t] += rx[t + off]; ry[t] += ry[t + off]; rz[t] += rz[t + off]; }
        __syncthreads();
    }
    if (t == 0) {
        g_mean[0] = rx[0] / (float)NV_;
        g_mean[1] = ry[0] / (float)NV_;
        g_mean[2] = rz[0] / (float)NV_;
    }
    float ax = coeff[t * CST + 224], ay = coeff[t * CST + 225], az = coeff[t * CST + 226];
    float sx = sinf(ax), cx = cosf(ax);
    float sy = sinf(ay), cy = cosf(ay);
    float sz = sinf(az), cz = cosf(az);
    float* M = g_rot + t * 9;
    M[0] = cz * cy;  M[1] = cz * sy * sx - sz * cx;  M[2] = cz * sy * cx + sz * sx;
    M[3] = sz * cy;  M[4] = sz * sy * sx + cz * cx;  M[5] = sz * sy * cx - cz * sx;
    M[6] = -sy;      M[7] = cy * sx;                 M[8] = cy * cx;
}

// ============================================================
__global__ void k_coeffT(const float* __restrict__ coeff)
{
    int j = blockIdx.x;
    int b = threadIdx.x;
    g_coeffT[j * B_ + b] = coeff[b * CST + j];
}

// ============================================================
// K_gemm: block 96 rows x 256 batches, thread tile 6x16 (f32x2)
// fused epilogue: face_shape store + projection to dout + tex store
// ============================================================
__device__ __forceinline__ void gemm_pass(
    const float* __restrict__ base, int kdim, int nch, int ctbase,
    int r0, int t, int rl, int bl,
    float (*sA)[96], float (*sB)[256], ull acc[6][8])
{
    for (int ch = 0; ch < nch; ++ch) {
        int koff = ch * 16;
        // A: 96 rows x 16 k, as float4 along k
        #pragma unroll
        for (int it = 0; it < 2; it++) {
            int idx = t + it * 256;
            if (idx < 384) {
                int row = idx >> 2, kq = idx & 3;
                int grow = r0 + row; if (grow >= NR_) grow = NR_ - 1;
                const float4 v = *reinterpret_cast<const float4*>(
                    base + (size_t)grow * kdim + koff + kq * 4);
                sA[kq * 4 + 0][row] = v.x;
                sA[kq * 4 + 1][row] = v.y;
                sA[kq * 4 + 2][row] = v.z;
                sA[kq * 4 + 3][row] = v.w;
            }
        }
        // B: 16 k x 256 b, float4
        #pragma unroll
        for (int it = 0; it < 4; it++) {
            int q = t + it * 256;           // 1024 quads
            int k = q >> 6, b = (q & 63) * 4;
            float4 v = *reinterpret_cast<const float4*>(
                g_coeffT + (size_t)(ctbase + koff + k) * B_ + b);
            *reinterpret_cast<float4*>(&sB[k][b]) = v;
        }
        __syncthreads();
        #pragma unroll
        for (int kk = 0; kk < 16; ++kk) {
            float2 a01 = *reinterpret_cast<const float2*>(&sA[kk][rl]);
            float2 a23 = *reinterpret_cast<const float2*>(&sA[kk][rl + 2]);
            float2 a45 = *reinterpret_cast<const float2*>(&sA[kk][rl + 4]);
            ull a2r[6];
            a2r[0] = dup2(a01.x); a2r[1] = dup2(a01.y);
            a2r[2] = dup2(a23.x); a2r[3] = dup2(a23.y);
            a2r[4] = dup2(a45.x); a2r[5] = dup2(a45.y);
            ulonglong2 p0 = *reinterpret_cast<const ulonglong2*>(&sB[kk][bl]);
            ulonglong2 p1 = *reinterpret_cast<const ulonglong2*>(&sB[kk][bl + 4]);
            ulonglong2 p2 = *reinterpret_cast<const ulonglong2*>(&sB[kk][bl + 8]);
            ulonglong2 p3 = *reinterpret_cast<const ulonglong2*>(&sB[kk][bl + 12]);
            ull bp[8] = {p0.x, p0.y, p1.x, p1.y, p2.x, p2.y, p3.x, p3.y};
            #pragma unroll
            for (int i = 0; i < 6; i++)
                #pragma unroll
                for (int j = 0; j < 8; j++)
                    acc[i][j] = fma2(a2r[i], bp[j], acc[i][j]);
        }
        __syncthreads();
    }
}

__global__ __launch_bounds__(256, 1) void k_gemm(
    const float* __restrict__ idBase, const float* __restrict__ exBase,
    const float* __restrict__ texBase, const float* __restrict__ meanshape,
    const float* __restrict__ meantex, const float* __restrict__ coeff,
    float* __restrict__ dout)
{
    __shared__ __align__(16) float sA[16][96];
    __shared__ __align__(16) float sB[16][256];
    __shared__ float srot[256][12];
    int t  = threadIdx.x;
    int r0 = blockIdx.x * 96;
    int rl = (t & 15) * 6;
    int bl = (t >> 4) * 16;

    // stage rotation + translation for all 256 batches
    for (int idx = t; idx < 256 * 12; idx += 256) {
        int b = idx / 12, k = idx % 12;
        srot[b][k] = (k < 9) ? g_rot[b * 9 + k] : coeff[b * CST + 254 + (k - 9)];
    }

    ull acc[6][8];
    #pragma unroll
    for (int i = 0; i < 6; i++)
        #pragma unroll
        for (int j = 0; j < 8; j++) acc[i][j] = 0ull;

    gemm_pass(idBase, 80, 5, 0,   r0, t, rl, bl, sA, sB, acc);
    gemm_pass(exBase, 64, 4, 80,  r0, t, rl, bl, sA, sB, acc);

    // ---- epilogue: centered face_shape + projection ----
    float cen[6][16];
    #pragma unroll
    for (int i = 0; i < 6; i++) {
        int row = r0 + rl + i;
        if (row < NR_) {
            float add = meanshape[row] - g_mean[row - (row / 3) * 3];
            #pragma unroll
            for (int j = 0; j < 8; j++) {
                float lo, hi;
                unpack2(acc[i][j], lo, hi);
                cen[i][2 * j] = lo + add; cen[i][2 * j + 1] = hi + add;
            }
            float* p = g_face_shape + (size_t)row * B_ + bl;
            #pragma unroll
            for (int q = 0; q < 4; q++)
                *reinterpret_cast<float4*>(p + q * 4) =
                    make_float4(cen[i][4 * q], cen[i][4 * q + 1],
                                cen[i][4 * q + 2], cen[i][4 * q + 3]);
        }
    }
    {
        int v_base = (r0 + rl) / 3;        // 2 consecutive vertices
        bool ok0 = (v_base < NV_), ok1 = (v_base + 1 < NV_);
        #pragma unroll
        for (int j = 0; j < 16; j++) {
            int b = bl + j;
            const float* R = srot[b];
            float m0 = R[0], m1 = R[1], m2 = R[2];
            float m3 = R[3], m4 = R[4], m5 = R[5];
            float m6 = R[6], m7 = R[7], m8 = R[8];
            float tx = R[9], ty = R[10], tz = R[11];
            if (ok0) {
                float x = cen[0][j + (j >= 8 ? 0 : 0)]; // direct
                x = cen[0][j]; float y = cen[1][j], z = cen[2][j];
                float* o = dout + (size_t)b * NR_ + (size_t)v_base * 3;
                o[0] = fmaf(m0, x, fmaf(m1, y, fmaf(m2, z, tx)));
                o[1] = fmaf(m3, x, fmaf(m4, y, fmaf(m5, z, ty)));
                o[2] = fmaf(m6, x, fmaf(m7, y, fmaf(m8, z, tz)));
            }
            if (ok1) {
                float x = cen[3][j], y = cen[4][j], z = cen[5][j];
                float* o = dout + (size_t)b * NR_ + (size_t)(v_base + 1) * 3;
                o[0] = fmaf(m0, x, fmaf(m1, y, fmaf(m2, z, tx)));
                o[1] = fmaf(m3, x, fmaf(m4, y, fmaf(m5, z, ty)));
                o[2] = fmaf(m6, x, fmaf(m7, y, fmaf(m8, z, tz)));
            }
        }
    }

    // ---- texture pass ----
    #pragma unroll
    for (int i = 0; i < 6; i++)
        #pragma unroll
        for (int j = 0; j < 8; j++) acc[i][j] = 0ull;

    gemm_pass(texBase, 80, 5, 144, r0, t, rl, bl, sA, sB, acc);

    #pragma unroll
    for (int i = 0; i < 6; i++) {
        int row = r0 + rl + i;
        if (row < NR_) {
            float mt = meantex[row];
            float o[16];
            #pragma unroll
            for (int j = 0; j < 8; j++) {
                float lo, hi;
                unpack2(acc[i][j], lo, hi);
                o[2 * j] = lo + mt; o[2 * j + 1] = hi + mt;
            }
            float* p = g_tex + (size_t)row * B_ + bl;
            #pragma unroll
            for (int q = 0; q < 4; q++)
                *reinterpret_cast<float4*>(p + q * 4) =
                    make_float4(o[4 * q], o[4 * q + 1], o[4 * q + 2], o[4 * q + 3]);
        }
    }
}

// ============================================================
// K_face_norm(g): 2 faces per thread, 32 batches
// ============================================================
__global__ void k_face_norm(int g)
{
    int t = threadIdx.x;
    int pair = blockIdx.x * 8 + (t >> 5);
    int b = g * 32 + (t & 31);
    #pragma unroll
    for (int u = 0; u < 2; u++) {
        int fid = pair * 2 + u;
        if (fid > NF_) continue;
        float* fn = g_face_norm + (size_t)(fid * 3) * B_ + b;
        if (fid == NF_) {
            fn[0] = 0.f; fn[B_] = 0.f; fn[2 * B_] = 0.f;
            continue;
        }
        int i0 = g_tri[fid * 3 + 0], i1 = g_tri[fid * 3 + 1], i2 = g_tri[fid * 3 + 2];
        const float* fs = g_face_shape;
        size_t o0 = (size_t)(3 * i0) * B_ + b;
        size_t o1 = (size_t)(3 * i1) * B_ + b;
        size_t o2 = (size_t)(3 * i2) * B_ + b;
        float v1x = fs[o0], v1y = fs[o0 + B_], v1z = fs[o0 + 2 * B_];
        float v2x = fs[o1], v2y = fs[o1 + B_], v2z = fs[o1 + 2 * B_];
        float v3x = fs[o2], v3y = fs[o2 + B_], v3z = fs[o2 + 2 * B_];
        float e1x = v1x - v2x, e1y = v1y - v2y, e1z = v1z - v2z;
        float e2x = v2x - v3x, e2y = v2y - v3y, e2z = v2z - v3z;
        fn[0]      = e1y * e2z - e1z * e2y;
        fn[B_]     = e1z * e2x - e1x * e2z;
        fn[2 * B_] = e1x * e2y - e1y * e2x;
    }
}

// ============================================================
// K_color(g): vertex normal sum + SH lighting + clamp
// ============================================================
__global__ void k_color(int g, const float* __restrict__ coeff,
                        float* __restrict__ dout)
{
    const float A0C0   = 0.88622692545275801f;
    const float A1C1   = 1.77245385090551603f;
    const float A2C2   = 2.42703222385900050f;
    const float A2C2D0 = 0.70062326950125306f;
    const float A2C2H  = 1.21351611192950025f;

    __shared__ float sc[96][33];
    __shared__ float sg[32][27];
    int t = threadIdx.x;
    int v0 = blockIdx.x * 32;

    for (int idx = t; idx < 32 * 27; idx += 256) {
        int b_l = idx / 27, kk = idx % 27;
        int k = kk / 3, c = kk % 3;
        float gv = coeff[(size_t)(g * 32 + b_l) * CST + 227 + c * 9 + k];
        if (k == 0) gv += 0.8f;
        sg[b_l][k * 3 + c] = gv;
    }
    __syncthreads();

    int vslot = t >> 5, b_l = t & 31;
    int b = g * 32 + b_l;
    #pragma unroll
    for (int it = 0; it < 4; it++) {
        int v_l = vslot + it * 8;
        int v = v0 + v_l;
        if (v < NV_) {
            const int4* pb4 = reinterpret_cast<const int4*>(g_pbuf + v * 8);
            int4 pa = pb4[0], pbv = pb4[1];
            int f[8] = {pa.x, pa.y, pa.z, pa.w, pbv.x, pbv.y, pbv.z, pbv.w};
            float sx = 0.f, sy = 0.f, sz = 0.f;
            #pragma unroll
            for (int i = 0; i < 8; i++) {
                const float* fn = g_face_norm + (size_t)(f[i] * 3) * B_ + b;
                sx += fn[0]; sy += fn[B_]; sz += fn[2 * B_];
            }
            float inv = rsqrtf(sx * sx + sy * sy + sz * sz);
            float nx = sx * inv, ny = sy * inv, nz = sz * inv;

            float Y[9];
            Y[0] = A0C0;
            Y[1] = -A1C1 * ny;
            Y[2] =  A1C1 * nz;
            Y[3] = -A1C1 * nx;
            Y[4] =  A2C2 * nx * ny;
            Y[5] = -A2C2 * ny * nz;
            Y[6] =  A2C2D0 * (3.f * nz * nz - 1.f);
            Y[7] = -A2C2 * nx * nz;
            Y[8] =  A2C2H * (nx * nx - ny * ny);

            const float* tx = g_tex + (size_t)(v * 3) * B_ + b;
            #pragma unroll
            for (int c = 0; c < 3; c++) {
                float l = 0.f;
                #pragma unroll
                for (int k = 0; k < 9; k++) l = fmaf(Y[k], sg[b_l][k * 3 + c], l);
                float col = tx[(size_t)c * B_] * l * (1.f / 255.f);
                sc[v_l * 3 + c][b_l] = fminf(fmaxf(col, 0.f), 1.f);
            }
        }
    }
    __syncthreads();

    int b_l2 = t >> 3, j = t & 7;
    int b2 = g * 32 + b_l2;
    #pragma unroll
    for (int w = 0; w < 4; w++) {
        int v_l = j * 4 + w;
        int v = v0 + v_l;
        if (v < NV_) {
            float* o = dout + OUT_COLOR + (size_t)b2 * NR_ + (size_t)v * 3;
            o[0] = sc[v_l * 3 + 0][b_l2];
            o[1] = sc[v_l * 3 + 1][b_l2];
            o[2] = sc[v_l * 3 + 2][b_l2];
        }
    }
}

// ============================================================
__global__ void k_tail(float* __restrict__ dout)
{
    int i = blockIdx.x * 256 + threadIdx.x;
    const int LM_N = B_ * NK_ * 3;
    if (i < LM_N) {
        int d = i % 3, r = i / 3;
        int k = r % NK_, b = r / NK_;
        int v = g_kp[k];
        dout[OUT_LM + i] = dout[(size_t)b * NR_ + (size_t)v * 3 + d];
    } else {
        int q = i - LM_N;
        if (q < NF_ * 3) dout[OUT_TRI + q] = (float)g_tri[q];
    }
}

// ============================================================
extern "C" void kernel_launch(void* const* d_in, const int* in_sizes, int n_in,
                              void* d_out, int out_size)
{
    (void)in_sizes; (void)n_in; (void)out_size;
    const float* coeff     = (const float*)d_in[0];
    const float* meanshape = (const float*)d_in[1];
    const float* idBase    = (const float*)d_in[2];
    const float* exBase    = (const float*)d_in[3];
    const float* meantex   = (const float*)d_in[4];
    const float* texBase   = (const float*)d_in[5];
    const void*  tri       = d_in[6];
    const void*  pbuf      = d_in[7];
    const void*  kp        = d_in[8];
    float* dout = (float*)d_out;

    k_idx   <<<128, 256>>>(tri, pbuf, kp);
    k_prep  <<<1, 256>>>(coeff, meanshape);
    k_coeffT<<<224, 256>>>(coeff);
    k_gemm  <<<(NR_ + 95) / 96, 256>>>(idBase, exBase, texBase,
                                       meanshape, meantex, coeff, dout);
    for (int g = 0; g < 8; g++) {
        k_face_norm<<<(NF_ / 2 + 8) / 8, 256>>>(g);
        k_color    <<<(NV_ + 31) / 32, 256>>>(g, coeff, dout);
    }
    k_tail<<<(B_ * NK_ * 3 + NF_ * 3 + 255) / 256, 256>>>(dout);
}

// round 4
// speedup vs baseline: 1.0869x; 1.0869x over previous
#include <cuda_runtime.h>
#include <math.h>

#define B_  256
#define NV_ 35709
#define NR_ 107127          // NV*3
#define NF_ 70789
#define NK_ 68
#define CST 257

#define OUT_COLOR ((size_t)B_ * NR_)
#define OUT_LM    ((size_t)2 * B_ * NR_)
#define OUT_TRI   (OUT_LM + (size_t)B_ * NK_ * 3)

#define NTEX  ((NR_ + 63) / 64)          // 1674 tex-gemm blocks
#define NPROJ (((NV_ + 31) / 32) * 8)    // 8928 proj blocks
#define NFN   (((NF_ + 1) / 2 + 8) / 8)  // 4425 fn blocks per group
#define NCOL  ((NV_ + 31) / 32)          // 1116 color blocks per group

typedef unsigned long long ull;

// -------- device scratch --------
__device__ float g_mean[3];
__device__ float g_rot[B_ * 9];
__device__ float g_coeffT[224 * B_];
__device__ float g_face_shape[(size_t)NR_ * B_];           // [row][b]
__device__ float g_tex[(size_t)NR_ * B_];                  // [row][b]
__device__ float g_face_norm[(size_t)(NF_ + 1) * 3 * B_];  // [face*3+d][b]
__device__ int   g_tri[NF_ * 3];
__device__ int   g_pbuf[NV_ * 8];
__device__ int   g_kp[NK_];

// ---------- f32x2 helpers ----------
__device__ __forceinline__ ull fma2(ull a, ull b, ull c) {
    ull d;
    asm("fma.rn.f32x2 %0, %1, %2, %3;" : "=l"(d) : "l"(a), "l"(b), "l"(c));
    return d;
}
__device__ __forceinline__ ull dup2(float x) {
    ull d;
    asm("mov.b64 %0, {%1, %1};" : "=l"(d) : "f"(x));
    return d;
}
__device__ __forceinline__ void unpack2(ull v, float& lo, float& hi) {
    asm("mov.b64 {%0, %1}, %2;" : "=f"(lo), "=f"(hi) : "l"(v));
}

// ============================================================
__global__ void k_idx(const void* __restrict__ tri,
                      const void* __restrict__ pbuf,
                      const void* __restrict__ kp)
{
    const int* t32 = (const int*)tri;
    bool is64 = true;
    #pragma unroll
    for (int i = 1; i < 32; i += 2) is64 = is64 && (t32[i] == 0);

    int gid = blockIdx.x * blockDim.x + threadIdx.x;
    int stride = gridDim.x * blockDim.x;
    if (is64) {
        const long long* a = (const long long*)tri;
        for (int i = gid; i < NF_ * 3; i += stride) g_tri[i] = (int)a[i];
        const long long* b = (const long long*)pbuf;
        for (int i = gid; i < NV_ * 8; i += stride) g_pbuf[i] = (int)b[i];
        const long long* c = (const long long*)kp;
        for (int i = gid; i < NK_; i += stride) g_kp[i] = (int)c[i];
    } else {
        const int* a = (const int*)tri;
        for (int i = gid; i < NF_ * 3; i += stride) g_tri[i] = a[i];
        const int* b = (const int*)pbuf;
        for (int i = gid; i < NV_ * 8; i += stride) g_pbuf[i] = b[i];
        const int* c = (const int*)kp;
        for (int i = gid; i < NK_; i += stride) g_kp[i] = c[i];
    }
}

// ============================================================
__global__ void k_prep(const float* __restrict__ coeff,
                       const float* __restrict__ meanshape)
{
    __shared__ float rx[256], ry[256], rz[256];
    int t = threadIdx.x;
    float s0 = 0.f, s1 = 0.f, s2 = 0.f;
    for (int v = t; v < NV_; v += 256) {
        s0 += meanshape[v * 3 + 0];
        s1 += meanshape[v * 3 + 1];
        s2 += meanshape[v * 3 + 2];
    }
    rx[t] = s0; ry[t] = s1; rz[t] = s2;
    __syncthreads();
    for (int off = 128; off > 0; off >>= 1) {
        if (t < off) { rx[t] += rx[t + off]; ry[t] += ry[t + off]; rz[t] += rz[t + off]; }
        __syncthreads();
    }
    if (t == 0) {
        g_mean[0] = rx[0] / (float)NV_;
        g_mean[1] = ry[0] / (float)NV_;
        g_mean[2] = rz[0] / (float)NV_;
    }
    float ax = coeff[t * CST + 224], ay = coeff[t * CST + 225], az = coeff[t * CST + 226];
    float sx = sinf(ax), cx = cosf(ax);
    float sy = sinf(ay), cy = cosf(ay);
    float sz = sinf(az), cz = cosf(az);
    float* M = g_rot + t * 9;
    M[0] = cz * cy;  M[1] = cz * sy * sx - sz * cx;  M[2] = cz * sy * cx + sz * sx;
    M[3] = sz * cy;  M[4] = sz * sy * sx + cz * cx;  M[5] = sz * sy * cx - cz * sx;
    M[6] = -sy;      M[7] = cy * sx;                 M[8] = cy * cx;
}

// ============================================================
__global__ void k_coeffT(const float* __restrict__ coeff)
{
    int j = blockIdx.x;
    int b = threadIdx.x;
    g_coeffT[j * B_ + b] = coeff[b * CST + j];
}

// ============================================================
// GEMM core: block 64 rows x 256 batches, thread tile 4x16, f32x2
// sA = sm[0..1023]  (16 k x 64 rows), sB = sm[1024..5119] (16 k x 256 b)
// ============================================================
__device__ __forceinline__ void gemm_pass(
    const float* __restrict__ base, int kdim, int nch, int ctbase,
    int r0, int t, int rl, int bl, float* sm, ull acc[4][8])
{
    float* sA = sm;
    float* sB = sm + 1024;
    for (int ch = 0; ch < nch; ++ch) {
        int koff = ch * 16;
        {
            int lr = t >> 2, kq = t & 3;
            int row = r0 + lr; if (row >= NR_) row = NR_ - 1;
            const float4 v = *reinterpret_cast<const float4*>(
                base + (size_t)row * kdim + koff + kq * 4);
            sA[(kq * 4 + 0) * 64 + lr] = v.x;
            sA[(kq * 4 + 1) * 64 + lr] = v.y;
            sA[(kq * 4 + 2) * 64 + lr] = v.z;
            sA[(kq * 4 + 3) * 64 + lr] = v.w;
        }
        #pragma unroll
        for (int it = 0; it < 4; it++) {
            int q = t + it * 256;               // 1024 quads
            int k = q >> 6, b = (q & 63) * 4;
            float4 v = *reinterpret_cast<const float4*>(
                g_coeffT + (size_t)(ctbase + koff + k) * B_ + b);
            *reinterpret_cast<float4*>(&sB[k * 256 + b]) = v;
        }
        __syncthreads();
        #pragma unroll
        for (int kk = 0; kk < 16; ++kk) {
            float4 a = *reinterpret_cast<const float4*>(&sA[kk * 64 + rl]);
            ull a2[4];
            a2[0] = dup2(a.x); a2[1] = dup2(a.y); a2[2] = dup2(a.z); a2[3] = dup2(a.w);
            ulonglong2 p0 = *reinterpret_cast<const ulonglong2*>(&sB[kk * 256 + bl]);
            ulonglong2 p1 = *reinterpret_cast<const ulonglong2*>(&sB[kk * 256 + bl + 4]);
            ulonglong2 p2 = *reinterpret_cast<const ulonglong2*>(&sB[kk * 256 + bl + 8]);
            ulonglong2 p3 = *reinterpret_cast<const ulonglong2*>(&sB[kk * 256 + bl + 12]);
            ull bp[8] = {p0.x, p0.y, p1.x, p1.y, p2.x, p2.y, p3.x, p3.y};
            #pragma unroll
            for (int i = 0; i < 4; i++)
                #pragma unroll
                for (int j = 0; j < 8; j++)
                    acc[i][j] = fma2(a2[i], bp[j], acc[i][j]);
        }
        __syncthreads();
    }
}

__device__ __forceinline__ void gemm_store(
    float* __restrict__ dst, int r0, int rl, int bl,
    ull acc[4][8], const float* __restrict__ addvec, bool meancenter)
{
    #pragma unroll
    for (int i = 0; i < 4; i++) {
        int row = r0 + rl + i;
        if (row < NR_) {
            float add = addvec[row];
            if (meancenter) add -= g_mean[row - (row / 3) * 3];
            float o[16];
            #pragma unroll
            for (int j = 0; j < 8; j++) {
                float lo, hi;
                unpack2(acc[i][j], lo, hi);
                o[2 * j] = lo + add; o[2 * j + 1] = hi + add;
            }
            float* p = dst + (size_t)row * B_ + bl;
            #pragma unroll
            for (int q = 0; q < 4; q++)
                *reinterpret_cast<float4*>(p + q * 4) =
                    make_float4(o[4 * q], o[4 * q + 1], o[4 * q + 2], o[4 * q + 3]);
        }
    }
}

// ============================================================
// k_gemm_shape: idBase + exBase -> g_face_shape (mean-centered)
// ============================================================
__global__ __launch_bounds__(256, 2) void k_gemm_shape(
    const float* __restrict__ idBase, const float* __restrict__ exBase,
    const float* __restrict__ meanshape)
{
    __shared__ __align__(16) float sm[5120];
    int t  = threadIdx.x;
    int r0 = blockIdx.x * 64;
    int rl = (t & 15) * 4;
    int bl = (t >> 4) * 16;

    ull acc[4][8];
    #pragma unroll
    for (int i = 0; i < 4; i++)
        #pragma unroll
        for (int j = 0; j < 8; j++) acc[i][j] = 0ull;

    gemm_pass(idBase, 80, 5, 0,  r0, t, rl, bl, sm, acc);
    gemm_pass(exBase, 64, 4, 80, r0, t, rl, bl, sm, acc);
    gemm_store(g_face_shape, r0, rl, bl, acc, meanshape, true);
}

// ============================================================
// device blocks for the mixed kernels
// ============================================================
__device__ __forceinline__ void tex_gemm_block(
    int bx, const float* __restrict__ texBase,
    const float* __restrict__ meantex, float* sm)
{
    int t  = threadIdx.x;
    int r0 = bx * 64;
    int rl = (t & 15) * 4;
    int bl = (t >> 4) * 16;
    ull acc[4][8];
    #pragma unroll
    for (int i = 0; i < 4; i++)
        #pragma unroll
        for (int j = 0; j < 8; j++) acc[i][j] = 0ull;
    gemm_pass(texBase, 80, 5, 144, r0, t, rl, bl, sm, acc);
    gemm_store(g_tex, r0, rl, bl, acc, meantex, false);
}

__device__ __forceinline__ void proj_block(
    int bx, const float* __restrict__ coeff, float* __restrict__ dout, float* sm)
{
    float* s    = sm;          // [96][33]
    float* srot = sm + 3200;   // [32][12]
    int t = threadIdx.x;
    int g = bx % 8;
    int v0 = (bx / 8) * 32;
    int r0 = v0 * 3;

    for (int idx = t; idx < 32 * 12; idx += 256) {
        int b_l = idx / 12, k = idx % 12;
        int b = g * 32 + b_l;
        srot[b_l * 12 + k] = (k < 9) ? g_rot[b * 9 + k] : coeff[b * CST + 254 + (k - 9)];
    }
    #pragma unroll
    for (int it = 0; it < 12; it++) {
        int idx = t + it * 256;
        int row = idx >> 5, b_l = idx & 31;
        s[row * 33 + b_l] = (r0 + row < NR_) ?
            g_face_shape[(size_t)(r0 + row) * B_ + g * 32 + b_l] : 0.f;
    }
    __syncthreads();

    int b_l = t >> 3, j = t & 7;
    int b = g * 32 + b_l;
    float m0 = srot[b_l * 12 + 0], m1 = srot[b_l * 12 + 1], m2 = srot[b_l * 12 + 2];
    float m3 = srot[b_l * 12 + 3], m4 = srot[b_l * 12 + 4], m5 = srot[b_l * 12 + 5];
    float m6 = srot[b_l * 12 + 6], m7 = srot[b_l * 12 + 7], m8 = srot[b_l * 12 + 8];
    float tx = srot[b_l * 12 + 9], ty = srot[b_l * 12 + 10], tz = srot[b_l * 12 + 11];
    #pragma unroll
    for (int w = 0; w < 4; w++) {
        int v_l = j * 4 + w;
        int v = v0 + v_l;
        if (v < NV_) {
            float x = s[(v_l * 3 + 0) * 33 + b_l];
            float y = s[(v_l * 3 + 1) * 33 + b_l];
            float z = s[(v_l * 3 + 2) * 33 + b_l];
            float* o = dout + (size_t)b * NR_ + (size_t)v * 3;
            o[0] = fmaf(m0, x, fmaf(m1, y, fmaf(m2, z, tx)));
            o[1] = fmaf(m3, x, fmaf(m4, y, fmaf(m5, z, ty)));
            o[2] = fmaf(m6, x, fmaf(m7, y, fmaf(m8, z, tz)));
        }
    }
}

__device__ __forceinline__ void fn_block(int bx, int g)
{
    int t = threadIdx.x;
    int pair = bx * 8 + (t >> 5);
    int b = g * 32 + (t & 31);
    #pragma unroll
    for (int u = 0; u < 2; u++) {
        int fid = pair * 2 + u;
        if (fid > NF_) continue;
        float* fn = g_face_norm + (size_t)(fid * 3) * B_ + b;
        if (fid == NF_) {
            fn[0] = 0.f; fn[B_] = 0.f; fn[2 * B_] = 0.f;
            continue;
        }
        int i0 = g_tri[fid * 3 + 0], i1 = g_tri[fid * 3 + 1], i2 = g_tri[fid * 3 + 2];
        const float* fs = g_face_shape;
        size_t o0 = (size_t)(3 * i0) * B_ + b;
        size_t o1 = (size_t)(3 * i1) * B_ + b;
        size_t o2 = (size_t)(3 * i2) * B_ + b;
        float v1x = fs[o0], v1y = fs[o0 + B_], v1z = fs[o0 + 2 * B_];
        float v2x = fs[o1], v2y = fs[o1 + B_], v2z = fs[o1 + 2 * B_];
        float v3x = fs[o2], v3y = fs[o2 + B_], v3z = fs[o2 + 2 * B_];
        float e1x = v1x - v2x, e1y = v1y - v2y, e1z = v1z - v2z;
        float e2x = v2x - v3x, e2y = v2y - v3y, e2z = v2z - v3z;
        fn[0]      = e1y * e2z - e1z * e2y;
        fn[B_]     = e1z * e2x - e1x * e2z;
        fn[2 * B_] = e1x * e2y - e1y * e2x;
    }
}

__device__ __forceinline__ void color_block(
    int bx, int g, const float* __restrict__ coeff,
    float* __restrict__ dout, float* sm)
{
    const float A0C0   = 0.88622692545275801f;
    const float A1C1   = 1.77245385090551603f;
    const float A2C2   = 2.42703222385900050f;
    const float A2C2D0 = 0.70062326950125306f;
    const float A2C2H  = 1.21351611192950025f;

    float* sc = sm;          // [96][33]
    float* sg = sm + 3200;   // [32][27]
    int t = threadIdx.x;
    int v0 = bx * 32;

    for (int idx = t; idx < 32 * 27; idx += 256) {
        int b_l = idx / 27, kk = idx % 27;
        int k = kk / 3, c = kk % 3;
        float gv = coeff[(size_t)(g * 32 + b_l) * CST + 227 + c * 9 + k];
        if (k == 0) gv += 0.8f;
        sg[b_l * 27 + k * 3 + c] = gv;
    }
    __syncthreads();

    int vslot = t >> 5, b_l = t & 31;
    int b = g * 32 + b_l;
    #pragma unroll
    for (int it = 0; it < 4; it++) {
        int v_l = vslot + it * 8;
        int v = v0 + v_l;
        if (v < NV_) {
            const int4* pb4 = reinterpret_cast<const int4*>(g_pbuf + v * 8);
            int4 pa = pb4[0], pbv = pb4[1];
            int f[8] = {pa.x, pa.y, pa.z, pa.w, pbv.x, pbv.y, pbv.z, pbv.w};
            float sx = 0.f, sy = 0.f, sz = 0.f;
            #pragma unroll
            for (int i = 0; i < 8; i++) {
                const float* fn = g_face_norm + (size_t)(f[i] * 3) * B_ + b;
                sx += fn[0]; sy += fn[B_]; sz += fn[2 * B_];
            }
            float inv = rsqrtf(sx * sx + sy * sy + sz * sz);
            float nx = sx * inv, ny = sy * inv, nz = sz * inv;

            float Y[9];
            Y[0] = A0C0;
            Y[1] = -A1C1 * ny;
            Y[2] =  A1C1 * nz;
            Y[3] = -A1C1 * nx;
            Y[4] =  A2C2 * nx * ny;
            Y[5] = -A2C2 * ny * nz;
            Y[6] =  A2C2D0 * (3.f * nz * nz - 1.f);
            Y[7] = -A2C2 * nx * nz;
            Y[8] =  A2C2H * (nx * nx - ny * ny);

            const float* tx = g_tex + (size_t)(v * 3) * B_ + b;
            #pragma unroll
            for (int c = 0; c < 3; c++) {
                float l = 0.f;
                #pragma unroll
                for (int k = 0; k < 9; k++) l = fmaf(Y[k], sg[b_l * 27 + k * 3 + c], l);
                float col = tx[(size_t)c * B_] * l * (1.f / 255.f);
                sc[(v_l * 3 + c) * 33 + b_l] = fminf(fmaxf(col, 0.f), 1.f);
            }
        }
    }
    __syncthreads();

    int b_l2 = t >> 3, j = t & 7;
    int b2 = g * 32 + b_l2;
    #pragma unroll
    for (int w = 0; w < 4; w++) {
        int v_l = j * 4 + w;
        int v = v0 + v_l;
        if (v < NV_) {
            float* o = dout + OUT_COLOR + (size_t)b2 * NR_ + (size_t)v * 3;
            o[0] = sc[(v_l * 3 + 0) * 33 + b_l2];
            o[1] = sc[(v_l * 3 + 1) * 33 + b_l2];
            o[2] = sc[(v_l * 3 + 2) * 33 + b_l2];
        }
    }
}

// ============================================================
// k_mix1: tex-gemm blocks + proj blocks + fn(group 0) blocks
// ============================================================
__global__ __launch_bounds__(256, 2) void k_mix1(
    const float* __restrict__ texBase, const float* __restrict__ meantex,
    const float* __restrict__ coeff, float* __restrict__ dout)
{
    __shared__ __align__(16) float sm[5120];
    int bx = blockIdx.x;
    if (bx < NTEX) {
        tex_gemm_block(bx, texBase, meantex, sm);
    } else if (bx < NTEX + NPROJ) {
        proj_block(bx - NTEX, coeff, dout, sm);
    } else {
        fn_block(bx - NTEX - NPROJ, 0);
    }
}

// ============================================================
// k_stage(g): color(g) blocks + fn(g+1) blocks
// ============================================================
__global__ void k_stage(int g, const float* __restrict__ coeff,
                        float* __restrict__ dout)
{
    __shared__ __align__(16) float sm[4096];
    int bx = blockIdx.x;
    if (bx < NCOL) {
        color_block(bx, g, coeff, dout, sm);
    } else {
        fn_block(bx - NCOL, g + 1);
    }
}

// ============================================================
__global__ void k_tail(float* __restrict__ dout)
{
    int i = blockIdx.x * 256 + threadIdx.x;
    const int LM_N = B_ * NK_ * 3;
    if (i < LM_N) {
        int d = i % 3, r = i / 3;
        int k = r % NK_, b = r / NK_;
        int v = g_kp[k];
        dout[OUT_LM + i] = dout[(size_t)b * NR_ + (size_t)v * 3 + d];
    } else {
        int q = i - LM_N;
        if (q < NF_ * 3) dout[OUT_TRI + q] = (float)g_tri[q];
    }
}

// ============================================================
extern "C" void kernel_launch(void* const* d_in, const int* in_sizes, int n_in,
                              void* d_out, int out_size)
{
    (void)in_sizes; (void)n_in; (void)out_size;
    const float* coeff     = (const float*)d_in[0];
    const float* meanshape = (const float*)d_in[1];
    const float* idBase    = (const float*)d_in[2];
    const float* exBase    = (const float*)d_in[3];
    const float* meantex   = (const float*)d_in[4];
    const float* texBase   = (const float*)d_in[5];
    const void*  tri       = d_in[6];
    const void*  pbuf      = d_in[7];
    const void*  kp        = d_in[8];
    float* dout = (float*)d_out;

    k_idx   <<<128, 256>>>(tri, pbuf, kp);
    k_prep  <<<1, 256>>>(coeff, meanshape);
    k_coeffT<<<224, 256>>>(coeff);
    k_gemm_shape<<<(NR_ + 63) / 64, 256>>>(idBase, exBase, meanshape);
    k_mix1 <<<NTEX + NPROJ + NFN, 256>>>(texBase, meantex, coeff, dout);
    for (int g = 0; g < 7; g++)
        k_stage<<<NCOL + NFN, 256>>>(g, coeff, dout);
    k_stage<<<NCOL, 256>>>(7, coeff, dout);
    k_tail<<<(B_ * NK_ * 3 + NF_ * 3 + 255) / 256, 256>>>(dout);
}

// round 6
// speedup vs baseline: 1.1658x; 1.0726x over previous
#include <cuda_runtime.h>
#include <cuda_bf16.h>
#include <math.h>
#include <stdint.h>

#define B_  256
#define NV_ 35709
#define NR_ 107127          // NV*3
#define NF_ 70789
#define NK_ 68
#define CST 257

#define OUT_COLOR ((size_t)B_ * NR_)
#define OUT_LM    ((size_t)2 * B_ * NR_)
#define OUT_TRI   (OUT_LM + (size_t)B_ * NK_ * 3)

#define NPROJ (((NV_ + 31) / 32) * 8)    // 8928 proj blocks
#define NFN   (((NF_ + 1) / 2 + 8) / 8)  // 4425 fn blocks per group
#define NCOL  ((NV_ + 31) / 32)          // 1116 color blocks per group
#define NT64  ((NR_ + 63) / 64)          // 1674 gemm row tiles

// -------- device scratch --------
__device__ float g_mean[3];
__device__ float g_rot[B_ * 9];
__device__ uint2 g_Apk[(size_t)NR_ * 72];                  // shape base hi/lo bf16x2
__device__ uint2 g_Tpk[(size_t)NR_ * 40];                  // tex base hi/lo
__device__ uint2 g_Bpk[B_ * 112];                          // coeff hi/lo
__device__ float g_face_shape[(size_t)NR_ * B_];           // [row][b]
__device__ float g_tex[(size_t)NR_ * B_];                  // [row][b]
__device__ float g_face_norm[(size_t)(NF_ + 1) * 3 * B_];  // [face*3+d][b]
__device__ int   g_tri[NF_ * 3];
__device__ int   g_pbuf[NV_ * 8];
__device__ int   g_kp[NK_];

// bf16 hi/lo split of a float pair: hi = rn(a),rn(b); lo = rn(residual)
__device__ __forceinline__ void split2(float a, float b, uint32_t& hi, uint32_t& lo) {
    __nv_bfloat16 ah = __float2bfloat16_rn(a), bh = __float2bfloat16_rn(b);
    float ar = a - __bfloat162float(ah), br = b - __bfloat162float(bh);
    __nv_bfloat162 h = __halves2bfloat162(ah, bh);
    __nv_bfloat162 l = __halves2bfloat162(__float2bfloat16_rn(ar), __float2bfloat16_rn(br));
    hi = *reinterpret_cast<uint32_t*>(&h);
    lo = *reinterpret_cast<uint32_t*>(&l);
}

__device__ __forceinline__ void mma_bf16(float* c,
    uint32_t a0, uint32_t a1, uint32_t a2, uint32_t a3,
    uint32_t b0, uint32_t b1)
{
    asm volatile(
        "mma.sync.aligned.m16n8k16.row.col.f32.bf16.bf16.f32 "
        "{%0,%1,%2,%3}, {%4,%5,%6,%7}, {%8,%9}, {%0,%1,%2,%3};"
        : "+f"(c[0]), "+f"(c[1]), "+f"(c[2]), "+f"(c[3])
        : "r"(a0), "r"(a1), "r"(a2), "r"(a3), "r"(b0), "r"(b1));
}

// ============================================================
__global__ void k_idx(const void* __restrict__ tri,
                      const void* __restrict__ pbuf,
                      const void* __restrict__ kp)
{
    const int* t32 = (const int*)tri;
    bool is64 = true;
    #pragma unroll
    for (int i = 1; i < 32; i += 2) is64 = is64 && (t32[i] == 0);

    int gid = blockIdx.x * blockDim.x + threadIdx.x;
    int stride = gridDim.x * blockDim.x;
    if (is64) {
        const long long* a = (const long long*)tri;
        for (int i = gid; i < NF_ * 3; i += stride) g_tri[i] = (int)a[i];
        const long long* b = (const long long*)pbuf;
        for (int i = gid; i < NV_ * 8; i += stride) g_pbuf[i] = (int)b[i];
        const long long* c = (const long long*)kp;
        for (int i = gid; i < NK_; i += stride) g_kp[i] = (int)c[i];
    } else {
        const int* a = (const int*)tri;
        for (int i = gid; i < NF_ * 3; i += stride) g_tri[i] = a[i];
        const int* b = (const int*)pbuf;
        for (int i = gid; i < NV_ * 8; i += stride) g_pbuf[i] = b[i];
        const int* c = (const int*)kp;
        for (int i = gid; i < NK_; i += stride) g_kp[i] = c[i];
    }
}

// ============================================================
__global__ void k_prep(const float* __restrict__ coeff,
                       const float* __restrict__ meanshape)
{
    __shared__ float rx[256], ry[256], rz[256];
    int t = threadIdx.x;
    float s0 = 0.f, s1 = 0.f, s2 = 0.f;
    for (int v = t; v < NV_; v += 256) {
        s0 += meanshape[v * 3 + 0];
        s1 += meanshape[v * 3 + 1];
        s2 += meanshape[v * 3 + 2];
    }
    rx[t] = s0; ry[t] = s1; rz[t] = s2;
    __syncthreads();
    for (int off = 128; off > 0; off >>= 1) {
        if (t < off) { rx[t] += rx[t + off]; ry[t] += ry[t + off]; rz[t] += rz[t + off]; }
        __syncthreads();
    }
    if (t == 0) {
        g_mean[0] = rx[0] / (float)NV_;
        g_mean[1] = ry[0] / (float)NV_;
        g_mean[2] = rz[0] / (float)NV_;
    }
    float ax = coeff[t * CST + 224], ay = coeff[t * CST + 225], az = coeff[t * CST + 226];
    float sx = sinf(ax), cx = cosf(ax);
    float sy = sinf(ay), cy = cosf(ay);
    float sz = sinf(az), cz = cosf(az);
    float* M = g_rot + t * 9;
    M[0] = cz * cy;  M[1] = cz * sy * sx - sz * cx;  M[2] = cz * sy * cx + sz * sx;
    M[3] = sz * cy;  M[4] = sz * sy * sx + cz * cx;  M[5] = sz * sy * cx - cz * sx;
    M[6] = -sy;      M[7] = cy * sx;                 M[8] = cy * cx;
}

// ============================================================
// k_splitA: pack base matrices into hi/lo bf16x2 (k-pairs).
// g_Apk[row][0..71]: k 0..159 from idBase(80) then exBase(64)
// g_Tpk[row][0..39]: texBase(80)
// ============================================================
__global__ void k_splitA(const float* __restrict__ idBase,
                         const float* __restrict__ exBase,
                         const float* __restrict__ texBase)
{
    int row = blockIdx.x;
    int c = threadIdx.x;   // 0..111
    float2 v;
    if (c < 40)      v = *reinterpret_cast<const float2*>(idBase + (size_t)row * 80 + 2 * c);
    else if (c < 72) v = *reinterpret_cast<const float2*>(exBase + (size_t)row * 64 + 2 * c - 80);
    else             v = *reinterpret_cast<const float2*>(texBase + (size_t)row * 80 + 2 * (c - 72));
    uint32_t hi, lo;
    split2(v.x, v.y, hi, lo);
    if (c < 72) g_Apk[(size_t)row * 72 + c] = make_uint2(hi, lo);
    else        g_Tpk[(size_t)row * 40 + (c - 72)] = make_uint2(hi, lo);
}

// ============================================================
// k_coeffB: pack coeff[:,0:224] per batch into hi/lo bf16x2 k-pairs
// ============================================================
__global__ void k_coeffB(const float* __restrict__ coeff)
{
    int b = blockIdx.x, c = threadIdx.x;  // c: 0..111
    float x = coeff[b * CST + 2 * c];
    float y = coeff[b * CST + 2 * c + 1];
    uint32_t hi, lo;
    split2(x, y, hi, lo);
    g_Bpk[b * 112 + c] = make_uint2(hi, lo);
}

// ============================================================
// k_hmma: bf16-split tensor-core GEMM (mma.sync m16n8k16).
// blockIdx.x < NT64: face_shape (K=144); else face_texture (K=80).
// Block: 64 rows x 256 batches; 8 warps = 4 m-subtiles x 2 n-halves.
// Warp tile m16 x n128; 3-term hi/lo accumulation in fp32.
// ============================================================
__global__ __launch_bounds__(256, 2) void k_hmma(
    const float* __restrict__ meanshape, const float* __restrict__ meantex)
{
    int t = threadIdx.x;
    int w = t >> 5, lane = t & 31;
    int g = lane >> 2, tig = lane & 3;
    int wm = w & 3, wn = w >> 2;
    bool is_shape = (blockIdx.x < NT64);
    int tile = is_shape ? blockIdx.x : (blockIdx.x - NT64);
    int r0 = tile * 64;
    int nch = is_shape ? 9 : 5;
    int wpr = is_shape ? 72 : 40;
    const uint2* apk = is_shape ? g_Apk : g_Tpk;
    int kboff = is_shape ? 0 : 72;     // coeff word offset (tex starts at k=144)

    int row0 = r0 + wm * 16 + g;
    int row1 = row0 + 8;
    int lrow0 = row0 < NR_ ? row0 : NR_ - 1;
    int lrow1 = row1 < NR_ ? row1 : NR_ - 1;
    int n0 = wn * 128;

    float acc[16][4];
    #pragma unroll
    for (int j = 0; j < 16; ++j)
        #pragma unroll
        for (int q = 0; q < 4; ++q) acc[j][q] = 0.f;

    for (int c = 0; c < nch; ++c) {
        int kw = c * 8;
        uint2 a0 = apk[(size_t)lrow0 * wpr + kw + tig];
        uint2 a1 = apk[(size_t)lrow1 * wpr + kw + tig];
        uint2 a2 = apk[(size_t)lrow0 * wpr + kw + tig + 4];
        uint2 a3 = apk[(size_t)lrow1 * wpr + kw + tig + 4];
        const uint2* bbase = g_Bpk + (size_t)(n0 + g) * 112 + kboff + kw + tig;
        #pragma unroll
        for (int j = 0; j < 16; ++j) {
            const uint2* bp = bbase + (size_t)j * 8 * 112;
            uint2 b0 = bp[0];
            uint2 b1 = bp[4];
            mma_bf16(acc[j], a0.x, a1.x, a2.x, a3.x, b0.x, b1.x);  // hi*hi
            mma_bf16(acc[j], a0.x, a1.x, a2.x, a3.x, b0.y, b1.y);  // hi*lo
            mma_bf16(acc[j], a0.y, a1.y, a2.y, a3.y, b0.x, b1.x);  // lo*hi
        }
    }

    // ---- epilogue ----
    float add0 = 0.f, add1 = 0.f;
    float* dst;
    if (is_shape) {
        if (row0 < NR_) add0 = meanshape[row0] - g_mean[row0 % 3];
        if (row1 < NR_) add1 = meanshape[row1] - g_mean[row1 % 3];
        dst = g_face_shape;
    } else {
        if (row0 < NR_) add0 = meantex[row0];
        if (row1 < NR_) add1 = meantex[row1];
        dst = g_tex;
    }
    #pragma unroll
    for (int j = 0; j < 16; ++j) {
        int col = n0 + j * 8 + 2 * tig;
        if (row0 < NR_)
            *reinterpret_cast<float2*>(dst + (size_t)row0 * B_ + col) =
                make_float2(acc[j][0] + add0, acc[j][1] + add0);
        if (row1 < NR_)
            *reinterpret_cast<float2*>(dst + (size_t)row1 * B_ + col) =
                make_float2(acc[j][2] + add1, acc[j][3] + add1);
    }
}

// ============================================================
// gather-phase device blocks (identical to round-4 passing kernel)
// ============================================================
__device__ __forceinline__ void proj_block(
    int bx, const float* __restrict__ coeff, float* __restrict__ dout, float* sm)
{
    float* s    = sm;          // [96][33]
    float* srot = sm + 3200;   // [32][12]
    int t = threadIdx.x;
    int g = bx % 8;
    int v0 = (bx / 8) * 32;
    int r0 = v0 * 3;

    for (int idx = t; idx < 32 * 12; idx += 256) {
        int b_l = idx / 12, k = idx % 12;
        int b = g * 32 + b_l;
        srot[b_l * 12 + k] = (k < 9) ? g_rot[b * 9 + k] : coeff[b * CST + 254 + (k - 9)];
    }
    #pragma unroll
    for (int it = 0; it < 12; it++) {
        int idx = t + it * 256;
        int row = idx >> 5, b_l = idx & 31;
        s[row * 33 + b_l] = (r0 + row < NR_) ?
            g_face_shape[(size_t)(r0 + row) * B_ + g * 32 + b_l] : 0.f;
    }
    __syncthreads();

    int b_l = t >> 3, j = t & 7;
    int b = g * 32 + b_l;
    float m0 = srot[b_l * 12 + 0], m1 = srot[b_l * 12 + 1], m2 = srot[b_l * 12 + 2];
    float m3 = srot[b_l * 12 + 3], m4 = srot[b_l * 12 + 4], m5 = srot[b_l * 12 + 5];
    float m6 = srot[b_l * 12 + 6], m7 = srot[b_l * 12 + 7], m8 = srot[b_l * 12 + 8];
    float tx = srot[b_l * 12 + 9], ty = srot[b_l * 12 + 10], tz = srot[b_l * 12 + 11];
    #pragma unroll
    for (int w = 0; w < 4; w++) {
        int v_l = j * 4 + w;
        int v = v0 + v_l;
        if (v < NV_) {
            float x = s[(v_l * 3 + 0) * 33 + b_l];
            float y = s[(v_l * 3 + 1) * 33 + b_l];
            float z = s[(v_l * 3 + 2) * 33 + b_l];
            float* o = dout + (size_t)b * NR_ + (size_t)v * 3;
            o[0] = fmaf(m0, x, fmaf(m1, y, fmaf(m2, z, tx)));
            o[1] = fmaf(m3, x, fmaf(m4, y, fmaf(m5, z, ty)));
            o[2] = fmaf(m6, x, fmaf(m7, y, fmaf(m8, z, tz)));
        }
    }
}

__device__ __forceinline__ void fn_block(int bx, int g)
{
    int t = threadIdx.x;
    int pair = bx * 8 + (t >> 5);
    int b = g * 32 + (t & 31);
    #pragma unroll
    for (int u = 0; u < 2; u++) {
        int fid = pair * 2 + u;
        if (fid > NF_) continue;
        float* fn = g_face_norm + (size_t)(fid * 3) * B_ + b;
        if (fid == NF_) {
            fn[0] = 0.f; fn[B_] = 0.f; fn[2 * B_] = 0.f;
            continue;
        }
        int i0 = g_tri[fid * 3 + 0], i1 = g_tri[fid * 3 + 1], i2 = g_tri[fid * 3 + 2];
        const float* fs = g_face_shape;
        size_t o0 = (size_t)(3 * i0) * B_ + b;
        size_t o1 = (size_t)(3 * i1) * B_ + b;
        size_t o2 = (size_t)(3 * i2) * B_ + b;
        float v1x = fs[o0], v1y = fs[o0 + B_], v1z = fs[o0 + 2 * B_];
        float v2x = fs[o1], v2y = fs[o1 + B_], v2z = fs[o1 + 2 * B_];
        float v3x = fs[o2], v3y = fs[o2 + B_], v3z = fs[o2 + 2 * B_];
        float e1x = v1x - v2x, e1y = v1y - v2y, e1z = v1z - v2z;
        float e2x = v2x - v3x, e2y = v2y - v3y, e2z = v2z - v3z;
        fn[0]      = e1y * e2z - e1z * e2y;
        fn[B_]     = e1z * e2x - e1x * e2z;
        fn[2 * B_] = e1x * e2y - e1y * e2x;
    }
}

__device__ __forceinline__ void color_block(
    int bx, int g, const float* __restrict__ coeff,
    float* __restrict__ dout, float* sm)
{
    const float A0C0   = 0.88622692545275801f;
    const float A1C1   = 1.77245385090551603f;
    const float A2C2   = 2.42703222385900050f;
    const float A2C2D0 = 0.70062326950125306f;
    const float A2C2H  = 1.21351611192950025f;

    float* sc = sm;          // [96][33]
    float* sg = sm + 3200;   // [32][27]
    int t = threadIdx.x;
    int v0 = bx * 32;

    for (int idx = t; idx < 32 * 27; idx += 256) {
        int b_l = idx / 27, kk = idx % 27;
        int k = kk / 3, c = kk % 3;
        float gv = coeff[(size_t)(g * 32 + b_l) * CST + 227 + c * 9 + k];
        if (k == 0) gv += 0.8f;
        sg[b_l * 27 + k * 3 + c] = gv;
    }
    __syncthreads();

    int vslot = t >> 5, b_l = t & 31;
    int b = g * 32 + b_l;
    #pragma unroll
    for (int it = 0; it < 4; it++) {
        int v_l = vslot + it * 8;
        int v = v0 + v_l;
        if (v < NV_) {
            const int4* pb4 = reinterpret_cast<const int4*>(g_pbuf + v * 8);
            int4 pa = pb4[0], pbv = pb4[1];
            int f[8] = {pa.x, pa.y, pa.z, pa.w, pbv.x, pbv.y, pbv.z, pbv.w};
            float sx = 0.f, sy = 0.f, sz = 0.f;
            #pragma unroll
            for (int i = 0; i < 8; i++) {
                const float* fn = g_face_norm + (size_t)(f[i] * 3) * B_ + b;
                sx += fn[0]; sy += fn[B_]; sz += fn[2 * B_];
            }
            float inv = rsqrtf(sx * sx + sy * sy + sz * sz);
            float nx = sx * inv, ny = sy * inv, nz = sz * inv;

            float Y[9];
            Y[0] = A0C0;
            Y[1] = -A1C1 * ny;
            Y[2] =  A1C1 * nz;
            Y[3] = -A1C1 * nx;
            Y[4] =  A2C2 * nx * ny;
            Y[5] = -A2C2 * ny * nz;
            Y[6] =  A2C2D0 * (3.f * nz * nz - 1.f);
            Y[7] = -A2C2 * nx * nz;
            Y[8] =  A2C2H * (nx * nx - ny * ny);

            const float* tx = g_tex + (size_t)(v * 3) * B_ + b;
            #pragma unroll
            for (int c = 0; c < 3; c++) {
                float l = 0.f;
                #pragma unroll
                for (int k = 0; k < 9; k++) l = fmaf(Y[k], sg[b_l * 27 + k * 3 + c], l);
                float col = tx[(size_t)c * B_] * l * (1.f / 255.f);
                sc[(v_l * 3 + c) * 33 + b_l] = fminf(fmaxf(col, 0.f), 1.f);
            }
        }
    }
    __syncthreads();

    int b_l2 = t >> 3, j = t & 7;
    int b2 = g * 32 + b_l2;
    #pragma unroll
    for (int w = 0; w < 4; w++) {
        int v_l = j * 4 + w;
        int v = v0 + v_l;
        if (v < NV_) {
            float* o = dout + OUT_COLOR + (size_t)b2 * NR_ + (size_t)v * 3;
            o[0] = sc[(v_l * 3 + 0) * 33 + b_l2];
            o[1] = sc[(v_l * 3 + 1) * 33 + b_l2];
            o[2] = sc[(v_l * 3 + 2) * 33 + b_l2];
        }
    }
}

// ============================================================
__global__ void k_mix1(const float* __restrict__ coeff, float* __restrict__ dout)
{
    __shared__ __align__(16) float sm[3584];
    int bx = blockIdx.x;
    if (bx < NPROJ) {
        proj_block(bx, coeff, dout, sm);
    } else {
        fn_block(bx - NPROJ, 0);
    }
}

__global__ void k_stage(int g, const float* __restrict__ coeff,
                        float* __restrict__ dout)
{
    __shared__ __align__(16) float sm[4096];
    int bx = blockIdx.x;
    if (bx < NCOL) {
        color_block(bx, g, coeff, dout, sm);
    } else {
        fn_block(bx - NCOL, g + 1);
    }
}

// ============================================================
__global__ void k_tail(float* __restrict__ dout)
{
    int i = blockIdx.x * 256 + threadIdx.x;
    const int LM_N = B_ * NK_ * 3;
    if (i < LM_N) {
        int d = i % 3, r = i / 3;
        int k = r % NK_, b = r / NK_;
        int v = g_kp[k];
        dout[OUT_LM + i] = dout[(size_t)b * NR_ + (size_t)v * 3 + d];
    } else {
        int q = i - LM_N;
        if (q < NF_ * 3) dout[OUT_TRI + q] = (float)g_tri[q];
    }
}

// ============================================================
extern "C" void kernel_launch(void* const* d_in, const int* in_sizes, int n_in,
                              void* d_out, int out_size)
{
    (void)in_sizes; (void)n_in; (void)out_size;
    const float* coeff     = (const float*)d_in[0];
    const float* meanshape = (const float*)d_in[1];
    const float* idBase    = (const float*)d_in[2];
    const float* exBase    = (const float*)d_in[3];
    const float* meantex   = (const float*)d_in[4];
    const float* texBase   = (const float*)d_in[5];
    const void*  tri       = d_in[6];
    const void*  pbuf      = d_in[7];
    const void*  kp        = d_in[8];
    float* dout = (float*)d_out;

    k_idx    <<<128, 256>>>(tri, pbuf, kp);
    k_prep   <<<1, 256>>>(coeff, meanshape);
    k_coeffB <<<256, 112>>>(coeff);
    k_splitA <<<NR_, 112>>>(idBase, exBase, texBase);
    k_hmma   <<<2 * NT64, 256>>>(meanshape, meantex);
    k_mix1   <<<NPROJ + NFN, 256>>>(coeff, dout);
    for (int g = 0; g < 7; g++)
        k_stage<<<NCOL + NFN, 256>>>(g, coeff, dout);
    k_stage<<<NCOL, 256>>>(7, coeff, dout);
    k_tail<<<(B_ * NK_ * 3 + NF_ * 3 + 255) / 256, 256>>>(dout);
}

// round 7
// speedup vs baseline: 1.2637x; 1.0840x over previous
#include <cuda_runtime.h>
#include <cuda_bf16.h>
#include <math.h>
#include <stdint.h>

#define B_  256
#define NV_ 35709
#define NR_ 107127          // NV*3
#define NF_ 70789
#define NK_ 68
#define CST 257

#define OUT_COLOR ((size_t)B_ * NR_)
#define OUT_LM    ((size_t)2 * B_ * NR_)
#define OUT_TRI   (OUT_LM + (size_t)B_ * NK_ * 3)

#define NPROJ (((NV_ + 31) / 32) * 8)    // 8928 proj blocks
#define NFN   (((NF_ + 1) / 2 + 8) / 8)  // 4425 fn blocks per group
#define NCOL  ((NV_ + 31) / 32)          // 1116 color blocks per group
#define NT64  ((NR_ + 63) / 64)          // 1674 gemm row tiles

// -------- device scratch --------
__device__ float g_mean[3];
__device__ float g_rot[B_ * 9];
__device__ uint2 g_Bpk[B_ * 112];                          // coeff hi/lo
__device__ float g_face_shape[(size_t)NR_ * B_];           // [row][b]
__device__ float g_tex[(size_t)NR_ * B_];                  // [row][b]
__device__ float g_face_norm[(size_t)(NF_ + 1) * 3 * B_];  // [face*3+d][b]
__device__ int   g_tri[NF_ * 3];
__device__ int   g_pbuf[NV_ * 8];
__device__ int   g_kp[NK_];

// bf16 hi/lo split of a float pair: hi = rn(a),rn(b); lo = rn(residual)
__device__ __forceinline__ void split2(float a, float b, uint32_t& hi, uint32_t& lo) {
    __nv_bfloat16 ah = __float2bfloat16_rn(a), bh = __float2bfloat16_rn(b);
    float ar = a - __bfloat162float(ah), br = b - __bfloat162float(bh);
    __nv_bfloat162 h = __halves2bfloat162(ah, bh);
    __nv_bfloat162 l = __halves2bfloat162(__float2bfloat16_rn(ar), __float2bfloat16_rn(br));
    hi = *reinterpret_cast<uint32_t*>(&h);
    lo = *reinterpret_cast<uint32_t*>(&l);
}

// load fp32 pair from base matrix and split in-register
__device__ __forceinline__ uint2 load_split(const float* __restrict__ base,
                                            int kd, size_t row, int pair) {
    float2 v = *reinterpret_cast<const float2*>(base + row * kd + 2 * pair);
    uint32_t hi, lo;
    split2(v.x, v.y, hi, lo);
    return make_uint2(hi, lo);
}

__device__ __forceinline__ void mma_bf16(float* c,
    uint32_t a0, uint32_t a1, uint32_t a2, uint32_t a3,
    uint32_t b0, uint32_t b1)
{
    asm volatile(
        "mma.sync.aligned.m16n8k16.row.col.f32.bf16.bf16.f32 "
        "{%0,%1,%2,%3}, {%4,%5,%6,%7}, {%8,%9}, {%0,%1,%2,%3};"
        : "+f"(c[0]), "+f"(c[1]), "+f"(c[2]), "+f"(c[3])
        : "r"(a0), "r"(a1), "r"(a2), "r"(a3), "r"(b0), "r"(b1));
}

// ============================================================
__global__ void k_idx(const void* __restrict__ tri,
                      const void* __restrict__ pbuf,
                      const void* __restrict__ kp)
{
    const int* t32 = (const int*)tri;
    bool is64 = true;
    #pragma unroll
    for (int i = 1; i < 32; i += 2) is64 = is64 && (t32[i] == 0);

    int gid = blockIdx.x * blockDim.x + threadIdx.x;
    int stride = gridDim.x * blockDim.x;
    if (is64) {
        const long long* a = (const long long*)tri;
        for (int i = gid; i < NF_ * 3; i += stride) g_tri[i] = (int)a[i];
        const long long* b = (const long long*)pbuf;
        for (int i = gid; i < NV_ * 8; i += stride) g_pbuf[i] = (int)b[i];
        const long long* c = (const long long*)kp;
        for (int i = gid; i < NK_; i += stride) g_kp[i] = (int)c[i];
    } else {
        const int* a = (const int*)tri;
        for (int i = gid; i < NF_ * 3; i += stride) g_tri[i] = a[i];
        const int* b = (const int*)pbuf;
        for (int i = gid; i < NV_ * 8; i += stride) g_pbuf[i] = b[i];
        const int* c = (const int*)kp;
        for (int i = gid; i < NK_; i += stride) g_kp[i] = c[i];
    }
}

// ============================================================
__global__ void k_prep(const float* __restrict__ coeff,
                       const float* __restrict__ meanshape)
{
    __shared__ float rx[256], ry[256], rz[256];
    int t = threadIdx.x;
    float s0 = 0.f, s1 = 0.f, s2 = 0.f;
    for (int v = t; v < NV_; v += 256) {
        s0 += meanshape[v * 3 + 0];
        s1 += meanshape[v * 3 + 1];
        s2 += meanshape[v * 3 + 2];
    }
    rx[t] = s0; ry[t] = s1; rz[t] = s2;
    __syncthreads();
    for (int off = 128; off > 0; off >>= 1) {
        if (t < off) { rx[t] += rx[t + off]; ry[t] += ry[t + off]; rz[t] += rz[t + off]; }
        __syncthreads();
    }
    if (t == 0) {
        g_mean[0] = rx[0] / (float)NV_;
        g_mean[1] = ry[0] / (float)NV_;
        g_mean[2] = rz[0] / (float)NV_;
    }
    float ax = coeff[t * CST + 224], ay = coeff[t * CST + 225], az = coeff[t * CST + 226];
    float sx = sinf(ax), cx = cosf(ax);
    float sy = sinf(ay), cy = cosf(ay);
    float sz = sinf(az), cz = cosf(az);
    float* M = g_rot + t * 9;
    M[0] = cz * cy;  M[1] = cz * sy * sx - sz * cx;  M[2] = cz * sy * cx + sz * sx;
    M[3] = sz * cy;  M[4] = sz * sy * sx + cz * cx;  M[5] = sz * sy * cx - cz * sx;
    M[6] = -sy;      M[7] = cy * sx;                 M[8] = cy * cx;
}

// ============================================================
// k_coeffB: pack coeff[:,0:224] per batch into hi/lo bf16x2 k-pairs
// ============================================================
__global__ void k_coeffB(const float* __restrict__ coeff)
{
    int b = blockIdx.x, c = threadIdx.x;  // c: 0..111
    float x = coeff[b * CST + 2 * c];
    float y = coeff[b * CST + 2 * c + 1];
    uint32_t hi, lo;
    split2(x, y, hi, lo);
    g_Bpk[b * 112 + c] = make_uint2(hi, lo);
}

// ============================================================
// k_hmma: bf16-split tensor-core GEMM (mma.sync m16n8k16).
// A fragments loaded fp32 from the base matrices and split in-register
// (each A element is consumed by exactly one block: no reuse to stage).
// blockIdx.x < NT64: face_shape (K=144); else face_texture (K=80).
// Block: 64 rows x 256 batches; 8 warps = 4 m-subtiles x 2 n-halves.
// ============================================================
__global__ __launch_bounds__(256, 2) void k_hmma(
    const float* __restrict__ idBase, const float* __restrict__ exBase,
    const float* __restrict__ texBase,
    const float* __restrict__ meanshape, const float* __restrict__ meantex)
{
    int t = threadIdx.x;
    int w = t >> 5, lane = t & 31;
    int g = lane >> 2, tig = lane & 3;
    int wm = w & 3, wn = w >> 2;
    bool is_shape = (blockIdx.x < NT64);
    int tile = is_shape ? blockIdx.x : (blockIdx.x - NT64);
    int r0 = tile * 64;
    int nch = is_shape ? 9 : 5;
    int kboff = is_shape ? 0 : 72;     // coeff word offset (tex starts at k=144)

    int row0 = r0 + wm * 16 + g;
    int row1 = row0 + 8;
    size_t lrow0 = (size_t)(row0 < NR_ ? row0 : NR_ - 1);
    size_t lrow1 = (size_t)(row1 < NR_ ? row1 : NR_ - 1);
    int n0 = wn * 128;

    float acc[16][4];
    #pragma unroll
    for (int j = 0; j < 16; ++j)
        #pragma unroll
        for (int q = 0; q < 4; ++q) acc[j][q] = 0.f;

    for (int c = 0; c < nch; ++c) {
        int kw = c * 8;
        // pick base matrix for this 16-k chunk (chunks never straddle bases)
        const float* ab;
        int kd, poff;
        if (is_shape) {
            if (c < 5) { ab = idBase; kd = 80; poff = 0; }
            else       { ab = exBase; kd = 64; poff = 40; }
        } else       { ab = texBase; kd = 80; poff = 0; }
        int p0 = kw + tig - poff;
        uint2 a0 = load_split(ab, kd, lrow0, p0);
        uint2 a1 = load_split(ab, kd, lrow1, p0);
        uint2 a2 = load_split(ab, kd, lrow0, p0 + 4);
        uint2 a3 = load_split(ab, kd, lrow1, p0 + 4);

        const uint2* bbase = g_Bpk + (size_t)(n0 + g) * 112 + kboff + kw + tig;
        #pragma unroll
        for (int j = 0; j < 16; ++j) {
            const uint2* bp = bbase + (size_t)j * 8 * 112;
            uint2 b0 = bp[0];
            uint2 b1 = bp[4];
            mma_bf16(acc[j], a0.x, a1.x, a2.x, a3.x, b0.x, b1.x);  // hi*hi
            mma_bf16(acc[j], a0.x, a1.x, a2.x, a3.x, b0.y, b1.y);  // hi*lo
            mma_bf16(acc[j], a0.y, a1.y, a2.y, a3.y, b0.x, b1.x);  // lo*hi
        }
    }

    // ---- epilogue ----
    float add0 = 0.f, add1 = 0.f;
    float* dst;
    if (is_shape) {
        if (row0 < NR_) add0 = meanshape[row0] - g_mean[row0 % 3];
        if (row1 < NR_) add1 = meanshape[row1] - g_mean[row1 % 3];
        dst = g_face_shape;
    } else {
        if (row0 < NR_) add0 = meantex[row0];
        if (row1 < NR_) add1 = meantex[row1];
        dst = g_tex;
    }
    #pragma unroll
    for (int j = 0; j < 16; ++j) {
        int col = n0 + j * 8 + 2 * tig;
        if (row0 < NR_)
            *reinterpret_cast<float2*>(dst + (size_t)row0 * B_ + col) =
                make_float2(acc[j][0] + add0, acc[j][1] + add0);
        if (row1 < NR_)
            *reinterpret_cast<float2*>(dst + (size_t)row1 * B_ + col) =
                make_float2(acc[j][2] + add1, acc[j][3] + add1);
    }
}

// ============================================================
// gather-phase device blocks (identical to round-6 passing kernel)
// ============================================================
__device__ __forceinline__ void proj_block(
    int bx, const float* __restrict__ coeff, float* __restrict__ dout, float* sm)
{
    float* s    = sm;          // [96][33]
    float* srot = sm + 3200;   // [32][12]
    int t = threadIdx.x;
    int g = bx % 8;
    int v0 = (bx / 8) * 32;
    int r0 = v0 * 3;

    for (int idx = t; idx < 32 * 12; idx += 256) {
        int b_l = idx / 12, k = idx % 12;
        int b = g * 32 + b_l;
        srot[b_l * 12 + k] = (k < 9) ? g_rot[b * 9 + k] : coeff[b * CST + 254 + (k - 9)];
    }
    #pragma unroll
    for (int it = 0; it < 12; it++) {
        int idx = t + it * 256;
        int row = idx >> 5, b_l = idx & 31;
        s[row * 33 + b_l] = (r0 + row < NR_) ?
            g_face_shape[(size_t)(r0 + row) * B_ + g * 32 + b_l] : 0.f;
    }
    __syncthreads();

    int b_l = t >> 3, j = t & 7;
    int b = g * 32 + b_l;
    float m0 = srot[b_l * 12 + 0], m1 = srot[b_l * 12 + 1], m2 = srot[b_l * 12 + 2];
    float m3 = srot[b_l * 12 + 3], m4 = srot[b_l * 12 + 4], m5 = srot[b_l * 12 + 5];
    float m6 = srot[b_l * 12 + 6], m7 = srot[b_l * 12 + 7], m8 = srot[b_l * 12 + 8];
    float tx = srot[b_l * 12 + 9], ty = srot[b_l * 12 + 10], tz = srot[b_l * 12 + 11];
    #pragma unroll
    for (int w = 0; w < 4; w++) {
        int v_l = j * 4 + w;
        int v = v0 + v_l;
        if (v < NV_) {
            float x = s[(v_l * 3 + 0) * 33 + b_l];
            float y = s[(v_l * 3 + 1) * 33 + b_l];
            float z = s[(v_l * 3 + 2) * 33 + b_l];
            float* o = dout + (size_t)b * NR_ + (size_t)v * 3;
            o[0] = fmaf(m0, x, fmaf(m1, y, fmaf(m2, z, tx)));
            o[1] = fmaf(m3, x, fmaf(m4, y, fmaf(m5, z, ty)));
            o[2] = fmaf(m6, x, fmaf(m7, y, fmaf(m8, z, tz)));
        }
    }
}

__device__ __forceinline__ void fn_block(int bx, int g)
{
    int t = threadIdx.x;
    int pair = bx * 8 + (t >> 5);
    int b = g * 32 + (t & 31);
    #pragma unroll
    for (int u = 0; u < 2; u++) {
        int fid = pair * 2 + u;
        if (fid > NF_) continue;
        float* fn = g_face_norm + (size_t)(fid * 3) * B_ + b;
        if (fid == NF_) {
            fn[0] = 0.f; fn[B_] = 0.f; fn[2 * B_] = 0.f;
            continue;
        }
        int i0 = g_tri[fid * 3 + 0], i1 = g_tri[fid * 3 + 1], i2 = g_tri[fid * 3 + 2];
        const float* fs = g_face_shape;
        size_t o0 = (size_t)(3 * i0) * B_ + b;
        size_t o1 = (size_t)(3 * i1) * B_ + b;
        size_t o2 = (size_t)(3 * i2) * B_ + b;
        float v1x = fs[o0], v1y = fs[o0 + B_], v1z = fs[o0 + 2 * B_];
        float v2x = fs[o1], v2y = fs[o1 + B_], v2z = fs[o1 + 2 * B_];
        float v3x = fs[o2], v3y = fs[o2 + B_], v3z = fs[o2 + 2 * B_];
        float e1x = v1x - v2x, e1y = v1y - v2y, e1z = v1z - v2z;
        float e2x = v2x - v3x, e2y = v2y - v3y, e2z = v2z - v3z;
        fn[0]      = e1y * e2z - e1z * e2y;
        fn[B_]     = e1z * e2x - e1x * e2z;
        fn[2 * B_] = e1x * e2y - e1y * e2x;
    }
}

__device__ __forceinline__ void color_block(
    int bx, int g, const float* __restrict__ coeff,
    float* __restrict__ dout, float* sm)
{
    const float A0C0   = 0.88622692545275801f;
    const float A1C1   = 1.77245385090551603f;
    const float A2C2   = 2.42703222385900050f;
    const float A2C2D0 = 0.70062326950125306f;
    const float A2C2H  = 1.21351611192950025f;

    float* sc = sm;          // [96][33]
    float* sg = sm + 3200;   // [32][27]
    int t = threadIdx.x;
    int v0 = bx * 32;

    for (int idx = t; idx < 32 * 27; idx += 256) {
        int b_l = idx / 27, kk = idx % 27;
        int k = kk / 3, c = kk % 3;
        float gv = coeff[(size_t)(g * 32 + b_l) * CST + 227 + c * 9 + k];
        if (k == 0) gv += 0.8f;
        sg[b_l * 27 + k * 3 + c] = gv;
    }
    __syncthreads();

    int vslot = t >> 5, b_l = t & 31;
    int b = g * 32 + b_l;
    #pragma unroll
    for (int it = 0; it < 4; it++) {
        int v_l = vslot + it * 8;
        int v = v0 + v_l;
        if (v < NV_) {
            const int4* pb4 = reinterpret_cast<const int4*>(g_pbuf + v * 8);
            int4 pa = pb4[0], pbv = pb4[1];
            int f[8] = {pa.x, pa.y, pa.z, pa.w, pbv.x, pbv.y, pbv.z, pbv.w};
            float sx = 0.f, sy = 0.f, sz = 0.f;
            #pragma unroll
            for (int i = 0; i < 8; i++) {
                const float* fn = g_face_norm + (size_t)(f[i] * 3) * B_ + b;
                sx += fn[0]; sy += fn[B_]; sz += fn[2 * B_];
            }
            float inv = rsqrtf(sx * sx + sy * sy + sz * sz);
            float nx = sx * inv, ny = sy * inv, nz = sz * inv;

            float Y[9];
            Y[0] = A0C0;
            Y[1] = -A1C1 * ny;
            Y[2] =  A1C1 * nz;
            Y[3] = -A1C1 * nx;
            Y[4] =  A2C2 * nx * ny;
            Y[5] = -A2C2 * ny * nz;
            Y[6] =  A2C2D0 * (3.f * nz * nz - 1.f);
            Y[7] = -A2C2 * nx * nz;
            Y[8] =  A2C2H * (nx * nx - ny * ny);

            const float* tx = g_tex + (size_t)(v * 3) * B_ + b;
            #pragma unroll
            for (int c = 0; c < 3; c++) {
                float l = 0.f;
                #pragma unroll
                for (int k = 0; k < 9; k++) l = fmaf(Y[k], sg[b_l * 27 + k * 3 + c], l);
                float col = tx[(size_t)c * B_] * l * (1.f / 255.f);
                sc[(v_l * 3 + c) * 33 + b_l] = fminf(fmaxf(col, 0.f), 1.f);
            }
        }
    }
    __syncthreads();

    int b_l2 = t >> 3, j = t & 7;
    int b2 = g * 32 + b_l2;
    #pragma unroll
    for (int w = 0; w < 4; w++) {
        int v_l = j * 4 + w;
        int v = v0 + v_l;
        if (v < NV_) {
            float* o = dout + OUT_COLOR + (size_t)b2 * NR_ + (size_t)v * 3;
            o[0] = sc[(v_l * 3 + 0) * 33 + b_l2];
            o[1] = sc[(v_l * 3 + 1) * 33 + b_l2];
            o[2] = sc[(v_l * 3 + 2) * 33 + b_l2];
        }
    }
}

// ============================================================
__global__ void k_mix1(const float* __restrict__ coeff, float* __restrict__ dout)
{
    __shared__ __align__(16) float sm[3584];
    int bx = blockIdx.x;
    if (bx < NPROJ) {
        proj_block(bx, coeff, dout, sm);
    } else {
        fn_block(bx - NPROJ, 0);
    }
}

__global__ void k_stage(int g, const float* __restrict__ coeff,
                        float* __restrict__ dout)
{
    __shared__ __align__(16) float sm[4096];
    int bx = blockIdx.x;
    if (bx < NCOL) {
        color_block(bx, g, coeff, dout, sm);
    } else {
        fn_block(bx - NCOL, g + 1);
    }
}

// ============================================================
__global__ void k_tail(float* __restrict__ dout)
{
    int i = blockIdx.x * 256 + threadIdx.x;
    const int LM_N = B_ * NK_ * 3;
    if (i < LM_N) {
        int d = i % 3, r = i / 3;
        int k = r % NK_, b = r / NK_;
        int v = g_kp[k];
        dout[OUT_LM + i] = dout[(size_t)b * NR_ + (size_t)v * 3 + d];
    } else {
        int q = i - LM_N;
        if (q < NF_ * 3) dout[OUT_TRI + q] = (float)g_tri[q];
    }
}

// ============================================================
extern "C" void kernel_launch(void* const* d_in, const int* in_sizes, int n_in,
                              void* d_out, int out_size)
{
    (void)in_sizes; (void)n_in; (void)out_size;
    const float* coeff     = (const float*)d_in[0];
    const float* meanshape = (const float*)d_in[1];
    const float* idBase    = (const float*)d_in[2];
    const float* exBase    = (const float*)d_in[3];
    const float* meantex   = (const float*)d_in[4];
    const float* texBase   = (const float*)d_in[5];
    const void*  tri       = d_in[6];
    const void*  pbuf      = d_in[7];
    const void*  kp        = d_in[8];
    float* dout = (float*)d_out;

    k_idx    <<<128, 256>>>(tri, pbuf, kp);
    k_prep   <<<1, 256>>>(coeff, meanshape);
    k_coeffB <<<256, 112>>>(coeff);
    k_hmma   <<<2 * NT64, 256>>>(idBase, exBase, texBase, meanshape, meantex);
    k_mix1   <<<NPROJ + NFN, 256>>>(coeff, dout);
    for (int g = 0; g < 7; g++)
        k_stage<<<NCOL + NFN, 256>>>(g, coeff, dout);
    k_stage<<<NCOL, 256>>>(7, coeff, dout);
    k_tail<<<(B_ * NK_ * 3 + NF_ * 3 + 255) / 256, 256>>>(dout);
}

// round 8
// speedup vs baseline: 1.4200x; 1.1237x over previous
#include <cuda_runtime.h>
#include <cuda_bf16.h>
#include <math.h>
#include <stdint.h>

#define B_  256
#define NV_ 35709
#define NR_ 107127          // NV*3
#define NF_ 70789
#define NK_ 68
#define CST 257

#define OUT_COLOR ((size_t)B_ * NR_)
#define OUT_LM    ((size_t)2 * B_ * NR_)
#define OUT_TRI   (OUT_LM + (size_t)B_ * NK_ * 3)

#define NPROJ (((NV_ + 31) / 32) * 8)    // 8928 proj blocks
#define NFN   (((NF_ + 1) / 2 + 8) / 8)  // 4425 fn blocks per group
#define NCOL  ((NV_ + 31) / 32)          // 1116 color blocks per group
#define NT64  ((NR_ + 63) / 64)          // 1674 gemm row tiles

// -------- device scratch --------
__device__ float g_mean[3];
__device__ float g_rot[B_ * 9];
__device__ uint2 g_Bpk[B_ * 112];                          // coeff hi/lo (chunk-permuted)
__device__ float g_face_shape[(size_t)NR_ * B_];           // [row][b]
__device__ float g_tex[(size_t)NR_ * B_];                  // [row][b]
__device__ float g_face_norm[(size_t)(NF_ + 1) * 3 * B_];  // [face*3+d][b]
__device__ int   g_tri[NF_ * 3];
__device__ int   g_pbuf[NV_ * 8];
__device__ int   g_kp[NK_];

// bf16 hi/lo split of a float pair: hi = rn(a),rn(b); lo = rn(residual)
__device__ __forceinline__ void split2(float a, float b, uint32_t& hi, uint32_t& lo) {
    __nv_bfloat16 ah = __float2bfloat16_rn(a), bh = __float2bfloat16_rn(b);
    float ar = a - __bfloat162float(ah), br = b - __bfloat162float(bh);
    __nv_bfloat162 h = __halves2bfloat162(ah, bh);
    __nv_bfloat162 l = __halves2bfloat162(__float2bfloat16_rn(ar), __float2bfloat16_rn(br));
    hi = *reinterpret_cast<uint32_t*>(&h);
    lo = *reinterpret_cast<uint32_t*>(&l);
}

// load fp32 pair from base matrix and split in-register
__device__ __forceinline__ uint2 load_split(const float* __restrict__ base,
                                            int kd, size_t row, int pair) {
    float2 v = *reinterpret_cast<const float2*>(base + row * kd + 2 * pair);
    uint32_t hi, lo;
    split2(v.x, v.y, hi, lo);
    return make_uint2(hi, lo);
}

__device__ __forceinline__ void mma_bf16(float* c,
    uint32_t a0, uint32_t a1, uint32_t a2, uint32_t a3,
    uint32_t b0, uint32_t b1)
{
    asm volatile(
        "mma.sync.aligned.m16n8k16.row.col.f32.bf16.bf16.f32 "
        "{%0,%1,%2,%3}, {%4,%5,%6,%7}, {%8,%9}, {%0,%1,%2,%3};"
        : "+f"(c[0]), "+f"(c[1]), "+f"(c[2]), "+f"(c[3])
        : "r"(a0), "r"(a1), "r"(a2), "r"(a3), "r"(b0), "r"(b1));
}

// ============================================================
__global__ void k_idx(const void* __restrict__ tri,
                      const void* __restrict__ pbuf,
                      const void* __restrict__ kp)
{
    const int* t32 = (const int*)tri;
    bool is64 = true;
    #pragma unroll
    for (int i = 1; i < 32; i += 2) is64 = is64 && (t32[i] == 0);

    int gid = blockIdx.x * blockDim.x + threadIdx.x;
    int stride = gridDim.x * blockDim.x;
    if (is64) {
        const long long* a = (const long long*)tri;
        for (int i = gid; i < NF_ * 3; i += stride) g_tri[i] = (int)a[i];
        const long long* b = (const long long*)pbuf;
        for (int i = gid; i < NV_ * 8; i += stride) g_pbuf[i] = (int)b[i];
        const long long* c = (const long long*)kp;
        for (int i = gid; i < NK_; i += stride) g_kp[i] = (int)c[i];
    } else {
        const int* a = (const int*)tri;
        for (int i = gid; i < NF_ * 3; i += stride) g_tri[i] = a[i];
        const int* b = (const int*)pbuf;
        for (int i = gid; i < NV_ * 8; i += stride) g_pbuf[i] = b[i];
        const int* c = (const int*)kp;
        for (int i = gid; i < NK_; i += stride) g_kp[i] = c[i];
    }
}

// ============================================================
__global__ void k_prep(const float* __restrict__ coeff,
                       const float* __restrict__ meanshape)
{
    __shared__ float rx[256], ry[256], rz[256];
    int t = threadIdx.x;
    float s0 = 0.f, s1 = 0.f, s2 = 0.f;
    for (int v = t; v < NV_; v += 256) {
        s0 += meanshape[v * 3 + 0];
        s1 += meanshape[v * 3 + 1];
        s2 += meanshape[v * 3 + 2];
    }
    rx[t] = s0; ry[t] = s1; rz[t] = s2;
    __syncthreads();
    for (int off = 128; off > 0; off >>= 1) {
        if (t < off) { rx[t] += rx[t + off]; ry[t] += ry[t + off]; rz[t] += rz[t + off]; }
        __syncthreads();
    }
    if (t == 0) {
        g_mean[0] = rx[0] / (float)NV_;
        g_mean[1] = ry[0] / (float)NV_;
        g_mean[2] = rz[0] / (float)NV_;
    }
    float ax = coeff[t * CST + 224], ay = coeff[t * CST + 225], az = coeff[t * CST + 226];
    float sx = sinf(ax), cx = cosf(ax);
    float sy = sinf(ay), cy = cosf(ay);
    float sz = sinf(az), cz = cosf(az);
    float* M = g_rot + t * 9;
    M[0] = cz * cy;  M[1] = cz * sy * sx - sz * cx;  M[2] = cz * sy * cx + sz * sx;
    M[3] = sz * cy;  M[4] = sz * sy * sx + cz * cx;  M[5] = sz * sy * cx - cz * sx;
    M[6] = -sy;      M[7] = cy * sx;                 M[8] = cy * cx;
}

// ============================================================
// k_coeffB: pack coeff[:,0:224] hi/lo bf16x2, chunk-permuted so a
// fragment lane's words (w, w+4) are adjacent -> one LDG.128 in k_hmma.
// within-chunk position of word w: (w&3)*2 + (w>>2)
// ============================================================
__global__ void k_coeffB(const float* __restrict__ coeff)
{
    int b = blockIdx.x, c = threadIdx.x;  // c: 0..111
    float x = coeff[b * CST + 2 * c];
    float y = coeff[b * CST + 2 * c + 1];
    uint32_t hi, lo;
    split2(x, y, hi, lo);
    int w = c & 7;
    int pos = (c & ~7) + ((w & 3) * 2 + (w >> 2));
    g_Bpk[b * 112 + pos] = make_uint2(hi, lo);
}

// ============================================================
// k_hmma: bf16-split tensor-core GEMM (mma.sync m16n8k16).
// B fragments: one LDG.128 per lane per j (permuted layout).
// blockIdx.x < NT64: face_shape (K=144); else face_texture (K=80).
// Block: 64 rows x 256 batches; 8 warps = 4 m-subtiles x 2 n-halves.
// ============================================================
__global__ __launch_bounds__(256, 2) void k_hmma(
    const float* __restrict__ idBase, const float* __restrict__ exBase,
    const float* __restrict__ texBase,
    const float* __restrict__ meanshape, const float* __restrict__ meantex)
{
    int t = threadIdx.x;
    int w = t >> 5, lane = t & 31;
    int g = lane >> 2, tig = lane & 3;
    int wm = w & 3, wn = w >> 2;
    bool is_shape = (blockIdx.x < NT64);
    int tile = is_shape ? blockIdx.x : (blockIdx.x - NT64);
    int r0 = tile * 64;
    int nch = is_shape ? 9 : 5;
    int kboff = is_shape ? 0 : 72;     // coeff word offset (tex starts at k=144)

    int row0 = r0 + wm * 16 + g;
    int row1 = row0 + 8;
    size_t lrow0 = (size_t)(row0 < NR_ ? row0 : NR_ - 1);
    size_t lrow1 = (size_t)(row1 < NR_ ? row1 : NR_ - 1);
    int n0 = wn * 128;

    float acc[16][4];
    #pragma unroll
    for (int j = 0; j < 16; ++j)
        #pragma unroll
        for (int q = 0; q < 4; ++q) acc[j][q] = 0.f;

    for (int c = 0; c < nch; ++c) {
        int kw = c * 8;
        // pick base matrix for this 16-k chunk (chunks never straddle bases)
        const float* ab;
        int kd, poff;
        if (is_shape) {
            if (c < 5) { ab = idBase; kd = 80; poff = 0; }
            else       { ab = exBase; kd = 64; poff = 40; }
        } else       { ab = texBase; kd = 80; poff = 0; }
        int p0 = kw + tig - poff;
        uint2 a0 = load_split(ab, kd, lrow0, p0);
        uint2 a1 = load_split(ab, kd, lrow1, p0);
        uint2 a2 = load_split(ab, kd, lrow0, p0 + 4);
        uint2 a3 = load_split(ab, kd, lrow1, p0 + 4);

        const uint2* bbase = g_Bpk + (size_t)(n0 + g) * 112 + kboff + kw + 2 * tig;
        #pragma unroll
        for (int j = 0; j < 16; ++j) {
            uint4 bv = *reinterpret_cast<const uint4*>(bbase + (size_t)j * 8 * 112);
            // bv = {hi_w, lo_w, hi_w4, lo_w4}
            mma_bf16(acc[j], a0.x, a1.x, a2.x, a3.x, bv.x, bv.z);  // hi*hi
            mma_bf16(acc[j], a0.x, a1.x, a2.x, a3.x, bv.y, bv.w);  // hi*lo
            mma_bf16(acc[j], a0.y, a1.y, a2.y, a3.y, bv.x, bv.z);  // lo*hi
        }
    }

    // ---- epilogue ----
    float add0 = 0.f, add1 = 0.f;
    float* dst;
    if (is_shape) {
        if (row0 < NR_) add0 = meanshape[row0] - g_mean[row0 % 3];
        if (row1 < NR_) add1 = meanshape[row1] - g_mean[row1 % 3];
        dst = g_face_shape;
    } else {
        if (row0 < NR_) add0 = meantex[row0];
        if (row1 < NR_) add1 = meantex[row1];
        dst = g_tex;
    }
    #pragma unroll
    for (int j = 0; j < 16; ++j) {
        int col = n0 + j * 8 + 2 * tig;
        if (row0 < NR_)
            *reinterpret_cast<float2*>(dst + (size_t)row0 * B_ + col) =
                make_float2(acc[j][0] + add0, acc[j][1] + add0);
        if (row1 < NR_)
            *reinterpret_cast<float2*>(dst + (size_t)row1 * B_ + col) =
                make_float2(acc[j][2] + add1, acc[j][3] + add1);
    }
}

// ============================================================
// gather-phase device blocks (identical to round-7 passing kernel)
// ============================================================
__device__ __forceinline__ void proj_block(
    int bx, const float* __restrict__ coeff, float* __restrict__ dout, float* sm)
{
    float* s    = sm;          // [96][33]
    float* srot = sm + 3200;   // [32][12]
    int t = threadIdx.x;
    int g = bx % 8;
    int v0 = (bx / 8) * 32;
    int r0 = v0 * 3;

    for (int idx = t; idx < 32 * 12; idx += 256) {
        int b_l = idx / 12, k = idx % 12;
        int b = g * 32 + b_l;
        srot[b_l * 12 + k] = (k < 9) ? g_rot[b * 9 + k] : coeff[b * CST + 254 + (k - 9)];
    }
    #pragma unroll
    for (int it = 0; it < 12; it++) {
        int idx = t + it * 256;
        int row = idx >> 5, b_l = idx & 31;
        s[row * 33 + b_l] = (r0 + row < NR_) ?
            g_face_shape[(size_t)(r0 + row) * B_ + g * 32 + b_l] : 0.f;
    }
    __syncthreads();

    int b_l = t >> 3, j = t & 7;
    int b = g * 32 + b_l;
    float m0 = srot[b_l * 12 + 0], m1 = srot[b_l * 12 + 1], m2 = srot[b_l * 12 + 2];
    float m3 = srot[b_l * 12 + 3], m4 = srot[b_l * 12 + 4], m5 = srot[b_l * 12 + 5];
    float m6 = srot[b_l * 12 + 6], m7 = srot[b_l * 12 + 7], m8 = srot[b_l * 12 + 8];
    float tx = srot[b_l * 12 + 9], ty = srot[b_l * 12 + 10], tz = srot[b_l * 12 + 11];
    #pragma unroll
    for (int w = 0; w < 4; w++) {
        int v_l = j * 4 + w;
        int v = v0 + v_l;
        if (v < NV_) {
            float x = s[(v_l * 3 + 0) * 33 + b_l];
            float y = s[(v_l * 3 + 1) * 33 + b_l];
            float z = s[(v_l * 3 + 2) * 33 + b_l];
            float* o = dout + (size_t)b * NR_ + (size_t)v * 3;
            o[0] = fmaf(m0, x, fmaf(m1, y, fmaf(m2, z, tx)));
            o[1] = fmaf(m3, x, fmaf(m4, y, fmaf(m5, z, ty)));
            o[2] = fmaf(m6, x, fmaf(m7, y, fmaf(m8, z, tz)));
        }
    }
}

__device__ __forceinline__ void fn_block(int bx, int g)
{
    int t = threadIdx.x;
    int pair = bx * 8 + (t >> 5);
    int b = g * 32 + (t & 31);
    #pragma unroll
    for (int u = 0; u < 2; u++) {
        int fid = pair * 2 + u;
        if (fid > NF_) continue;
        float* fn = g_face_norm + (size_t)(fid * 3) * B_ + b;
        if (fid == NF_) {
            fn[0] = 0.f; fn[B_] = 0.f; fn[2 * B_] = 0.f;
            continue;
        }
        int i0 = g_tri[fid * 3 + 0], i1 = g_tri[fid * 3 + 1], i2 = g_tri[fid * 3 + 2];
        const float* fs = g_face_shape;
        size_t o0 = (size_t)(3 * i0) * B_ + b;
        size_t o1 = (size_t)(3 * i1) * B_ + b;
        size_t o2 = (size_t)(3 * i2) * B_ + b;
        float v1x = fs[o0], v1y = fs[o0 + B_], v1z = fs[o0 + 2 * B_];
        float v2x = fs[o1], v2y = fs[o1 + B_], v2z = fs[o1 + 2 * B_];
        float v3x = fs[o2], v3y = fs[o2 + B_], v3z = fs[o2 + 2 * B_];
        float e1x = v1x - v2x, e1y = v1y - v2y, e1z = v1z - v2z;
        float e2x = v2x - v3x, e2y = v2y - v3y, e2z = v2z - v3z;
        fn[0]      = e1y * e2z - e1z * e2y;
        fn[B_]     = e1z * e2x - e1x * e2z;
        fn[2 * B_] = e1x * e2y - e1y * e2x;
    }
}

__device__ __forceinline__ void color_block(
    int bx, int g, const float* __restrict__ coeff,
    float* __restrict__ dout, float* sm)
{
    const float A0C0   = 0.88622692545275801f;
    const float A1C1   = 1.77245385090551603f;
    const float A2C2   = 2.42703222385900050f;
    const float A2C2D0 = 0.70062326950125306f;
    const float A2C2H  = 1.21351611192950025f;

    float* sc = sm;          // [96][33]
    float* sg = sm + 3200;   // [32][27]
    int t = threadIdx.x;
    int v0 = bx * 32;

    for (int idx = t; idx < 32 * 27; idx += 256) {
        int b_l = idx / 27, kk = idx % 27;
        int k = kk / 3, c = kk % 3;
        float gv = coeff[(size_t)(g * 32 + b_l) * CST + 227 + c * 9 + k];
        if (k == 0) gv += 0.8f;
        sg[b_l * 27 + k * 3 + c] = gv;
    }
    __syncthreads();

    int vslot = t >> 5, b_l = t & 31;
    int b = g * 32 + b_l;
    #pragma unroll
    for (int it = 0; it < 4; it++) {
        int v_l = vslot + it * 8;
        int v = v0 + v_l;
        if (v < NV_) {
            const int4* pb4 = reinterpret_cast<const int4*>(g_pbuf + v * 8);
            int4 pa = pb4[0], pbv = pb4[1];
            int f[8] = {pa.x, pa.y, pa.z, pa.w, pbv.x, pbv.y, pbv.z, pbv.w};
            float sx = 0.f, sy = 0.f, sz = 0.f;
            #pragma unroll
            for (int i = 0; i < 8; i++) {
                const float* fn = g_face_norm + (size_t)(f[i] * 3) * B_ + b;
                sx += fn[0]; sy += fn[B_]; sz += fn[2 * B_];
            }
            float inv = rsqrtf(sx * sx + sy * sy + sz * sz);
            float nx = sx * inv, ny = sy * inv, nz = sz * inv;

            float Y[9];
            Y[0] = A0C0;
            Y[1] = -A1C1 * ny;
            Y[2] =  A1C1 * nz;
            Y[3] = -A1C1 * nx;
            Y[4] =  A2C2 * nx * ny;
            Y[5] = -A2C2 * ny * nz;
            Y[6] =  A2C2D0 * (3.f * nz * nz - 1.f);
            Y[7] = -A2C2 * nx * nz;
            Y[8] =  A2C2H * (nx * nx - ny * ny);

            const float* tx = g_tex + (size_t)(v * 3) * B_ + b;
            #pragma unroll
            for (int c = 0; c < 3; c++) {
                float l = 0.f;
                #pragma unroll
                for (int k = 0; k < 9; k++) l = fmaf(Y[k], sg[b_l * 27 + k * 3 + c], l);
                float col = tx[(size_t)c * B_] * l * (1.f / 255.f);
                sc[(v_l * 3 + c) * 33 + b_l] = fminf(fmaxf(col, 0.f), 1.f);
            }
        }
    }
    __syncthreads();

    int b_l2 = t >> 3, j = t & 7;
    int b2 = g * 32 + b_l2;
    #pragma unroll
    for (int w = 0; w < 4; w++) {
        int v_l = j * 4 + w;
        int v = v0 + v_l;
        if (v < NV_) {
            float* o = dout + OUT_COLOR + (size_t)b2 * NR_ + (size_t)v * 3;
            o[0] = sc[(v_l * 3 + 0) * 33 + b_l2];
            o[1] = sc[(v_l * 3 + 1) * 33 + b_l2];
            o[2] = sc[(v_l * 3 + 2) * 33 + b_l2];
        }
    }
}

// ============================================================
__global__ void k_mix1(const float* __restrict__ coeff, float* __restrict__ dout)
{
    __shared__ __align__(16) float sm[3584];
    int bx = blockIdx.x;
    if (bx < NPROJ) {
        proj_block(bx, coeff, dout, sm);
    } else {
        fn_block(bx - NPROJ, 0);
    }
}

__global__ void k_stage(int g, const float* __restrict__ coeff,
                        float* __restrict__ dout)
{
    __shared__ __align__(16) float sm[4096];
    int bx = blockIdx.x;
    if (bx < NCOL) {
        color_block(bx, g, coeff, dout, sm);
    } else {
        fn_block(bx - NCOL, g + 1);
    }
}

// ============================================================
__global__ void k_tail(float* __restrict__ dout)
{
    int i = blockIdx.x * 256 + threadIdx.x;
    const int LM_N = B_ * NK_ * 3;
    if (i < LM_N) {
        int d = i % 3, r = i / 3;
        int k = r % NK_, b = r / NK_;
        int v = g_kp[k];
        dout[OUT_LM + i] = dout[(size_t)b * NR_ + (size_t)v * 3 + d];
    } else {
        int q = i - LM_N;
        if (q < NF_ * 3) dout[OUT_TRI + q] = (float)g_tri[q];
    }
}

// ============================================================
extern "C" void kernel_launch(void* const* d_in, const int* in_sizes, int n_in,
                              void* d_out, int out_size)
{
    (void)in_sizes; (void)n_in; (void)out_size;
    const float* coeff     = (const float*)d_in[0];
    const float* meanshape = (const float*)d_in[1];
    const float* idBase    = (const float*)d_in[2];
    const float* exBase    = (const float*)d_in[3];
    const float* meantex   = (const float*)d_in[4];
    const float* texBase   = (const float*)d_in[5];
    const void*  tri       = d_in[6];
    const void*  pbuf      = d_in[7];
    const void*  kp        = d_in[8];
    float* dout = (float*)d_out;

    k_idx    <<<128, 256>>>(tri, pbuf, kp);
    k_prep   <<<1, 256>>>(coeff, meanshape);
    k_coeffB <<<256, 112>>>(coeff);
    k_hmma   <<<2 * NT64, 256>>>(idBase, exBase, texBase, meanshape, meantex);
    k_mix1   <<<NPROJ + NFN, 256>>>(coeff, dout);
    for (int g = 0; g < 7; g++)
        k_stage<<<NCOL + NFN, 256>>>(g, coeff, dout);
    k_stage<<<NCOL, 256>>>(7, coeff, dout);
    k_tail<<<(B_ * NK_ * 3 + NF_ * 3 + 255) / 256, 256>>>(dout);
}

// round 9
// speedup vs baseline: 1.4243x; 1.0030x over previous
#include <cuda_runtime.h>
#include <cuda_bf16.h>
#include <math.h>
#include <stdint.h>

#define B_  256
#define NV_ 35709
#define NR_ 107127          // NV*3
#define NF_ 70789
#define NK_ 68
#define CST 257

#define OUT_COLOR ((size_t)B_ * NR_)
#define OUT_LM    ((size_t)2 * B_ * NR_)
#define OUT_TRI   (OUT_LM + (size_t)B_ * NK_ * 3)

#define NPROJ (((NV_ + 31) / 32) * 8)    // 8928 proj blocks
#define NFN   ((NF_ + 1 + 31) / 32)      // 2213 fn blocks per group (32 faces/block)
#define NCOL  ((NV_ + 31) / 32)          // 1116 color blocks per group
#define NT64  ((NR_ + 63) / 64)          // 1674 gemm row tiles

// -------- device scratch --------
__device__ float g_mean[3];
__device__ float g_rot[B_ * 9];
__device__ uint2 g_Bpk[B_ * 112];                          // coeff hi/lo (chunk-permuted)
__device__ float g_face_shape[(size_t)NR_ * B_];           // [row][b]
__device__ float g_tex[(size_t)NR_ * B_];                  // [row][b]
__device__ float g_face_norm[(size_t)(NF_ + 1) * 3 * B_];  // [face*3+d][b]
__device__ int   g_tri[NF_ * 3];
__device__ int   g_pbuf[NV_ * 8];
__device__ int   g_kp[NK_];

// bf16 hi/lo split of a float pair: hi = rn(a),rn(b); lo = rn(residual)
__device__ __forceinline__ void split2(float a, float b, uint32_t& hi, uint32_t& lo) {
    __nv_bfloat16 ah = __float2bfloat16_rn(a), bh = __float2bfloat16_rn(b);
    float ar = a - __bfloat162float(ah), br = b - __bfloat162float(bh);
    __nv_bfloat162 h = __halves2bfloat162(ah, bh);
    __nv_bfloat162 l = __halves2bfloat162(__float2bfloat16_rn(ar), __float2bfloat16_rn(br));
    hi = *reinterpret_cast<uint32_t*>(&h);
    lo = *reinterpret_cast<uint32_t*>(&l);
}

// load fp32 pair from base matrix and split in-register
__device__ __forceinline__ uint2 load_split(const float* __restrict__ base,
                                            int kd, size_t row, int pair) {
    float2 v = *reinterpret_cast<const float2*>(base + row * kd + 2 * pair);
    uint32_t hi, lo;
    split2(v.x, v.y, hi, lo);
    return make_uint2(hi, lo);
}

__device__ __forceinline__ void mma_bf16(float* c,
    uint32_t a0, uint32_t a1, uint32_t a2, uint32_t a3,
    uint32_t b0, uint32_t b1)
{
    asm volatile(
        "mma.sync.aligned.m16n8k16.row.col.f32.bf16.bf16.f32 "
        "{%0,%1,%2,%3}, {%4,%5,%6,%7}, {%8,%9}, {%0,%1,%2,%3};"
        : "+f"(c[0]), "+f"(c[1]), "+f"(c[2]), "+f"(c[3])
        : "r"(a0), "r"(a1), "r"(a2), "r"(a3), "r"(b0), "r"(b1));
}

// ============================================================
__global__ void k_idx(const void* __restrict__ tri,
                      const void* __restrict__ pbuf,
                      const void* __restrict__ kp)
{
    const int* t32 = (const int*)tri;
    bool is64 = true;
    #pragma unroll
    for (int i = 1; i < 32; i += 2) is64 = is64 && (t32[i] == 0);

    int gid = blockIdx.x * blockDim.x + threadIdx.x;
    int stride = gridDim.x * blockDim.x;
    if (is64) {
        const long long* a = (const long long*)tri;
        for (int i = gid; i < NF_ * 3; i += stride) g_tri[i] = (int)a[i];
        const long long* b = (const long long*)pbuf;
        for (int i = gid; i < NV_ * 8; i += stride) g_pbuf[i] = (int)b[i];
        const long long* c = (const long long*)kp;
        for (int i = gid; i < NK_; i += stride) g_kp[i] = (int)c[i];
    } else {
        const int* a = (const int*)tri;
        for (int i = gid; i < NF_ * 3; i += stride) g_tri[i] = a[i];
        const int* b = (const int*)pbuf;
        for (int i = gid; i < NV_ * 8; i += stride) g_pbuf[i] = b[i];
        const int* c = (const int*)kp;
        for (int i = gid; i < NK_; i += stride) g_kp[i] = c[i];
    }
}

// ============================================================
__global__ void k_prep(const float* __restrict__ coeff,
                       const float* __restrict__ meanshape)
{
    __shared__ float rx[256], ry[256], rz[256];
    int t = threadIdx.x;
    float s0 = 0.f, s1 = 0.f, s2 = 0.f;
    for (int v = t; v < NV_; v += 256) {
        s0 += meanshape[v * 3 + 0];
        s1 += meanshape[v * 3 + 1];
        s2 += meanshape[v * 3 + 2];
    }
    rx[t] = s0; ry[t] = s1; rz[t] = s2;
    __syncthreads();
    for (int off = 128; off > 0; off >>= 1) {
        if (t < off) { rx[t] += rx[t + off]; ry[t] += ry[t + off]; rz[t] += rz[t + off]; }
        __syncthreads();
    }
    if (t == 0) {
        g_mean[0] = rx[0] / (float)NV_;
        g_mean[1] = ry[0] / (float)NV_;
        g_mean[2] = rz[0] / (float)NV_;
    }
    float ax = coeff[t * CST + 224], ay = coeff[t * CST + 225], az = coeff[t * CST + 226];
    float sx = sinf(ax), cx = cosf(ax);
    float sy = sinf(ay), cy = cosf(ay);
    float sz = sinf(az), cz = cosf(az);
    float* M = g_rot + t * 9;
    M[0] = cz * cy;  M[1] = cz * sy * sx - sz * cx;  M[2] = cz * sy * cx + sz * sx;
    M[3] = sz * cy;  M[4] = sz * sy * sx + cz * cx;  M[5] = sz * sy * cx - cz * sx;
    M[6] = -sy;      M[7] = cy * sx;                 M[8] = cy * cx;
}

// ============================================================
// k_coeffB: pack coeff[:,0:224] hi/lo bf16x2, chunk-permuted so a
// fragment lane's words (w, w+4) are adjacent -> one LDG.128 in k_hmma.
// ============================================================
__global__ void k_coeffB(const float* __restrict__ coeff)
{
    int b = blockIdx.x, c = threadIdx.x;  // c: 0..111
    float x = coeff[b * CST + 2 * c];
    float y = coeff[b * CST + 2 * c + 1];
    uint32_t hi, lo;
    split2(x, y, hi, lo);
    int w = c & 7;
    int pos = (c & ~7) + ((w & 3) * 2 + (w >> 2));
    g_Bpk[b * 112 + pos] = make_uint2(hi, lo);
}

// ============================================================
// k_hmma: bf16-split tensor-core GEMM (mma.sync m16n8k16).
// Warp tile m32 x n64 (2 m16 subtiles): per chunk A=8 LDG.64,
// B=8 LDG.128 (vs 16 at m16n128) for the same 48 MMAs.
// Block: 64 rows x 256 batches; 8 warps = 2 wm x 4 wn.
// ============================================================
__global__ __launch_bounds__(256, 2) void k_hmma(
    const float* __restrict__ idBase, const float* __restrict__ exBase,
    const float* __restrict__ texBase,
    const float* __restrict__ meanshape, const float* __restrict__ meantex)
{
    int t = threadIdx.x;
    int w = t >> 5, lane = t & 31;
    int g = lane >> 2, tig = lane & 3;
    int wm = w & 1, wn = w >> 1;
    bool is_shape = (blockIdx.x < NT64);
    int tile = is_shape ? blockIdx.x : (blockIdx.x - NT64);
    int r0 = tile * 64;
    int nch = is_shape ? 9 : 5;
    int kboff = is_shape ? 0 : 72;     // coeff word offset (tex starts at k=144)

    // 4 rows per lane: wm*32 + {0,8,16,24} + g
    int rw0 = r0 + wm * 32 + g;
    int rows[4] = {rw0, rw0 + 8, rw0 + 16, rw0 + 24};
    size_t lrows[4];
    #pragma unroll
    for (int s = 0; s < 4; ++s)
        lrows[s] = (size_t)(rows[s] < NR_ ? rows[s] : NR_ - 1);
    int n0 = wn * 64;

    float acc[8][8];   // [j][subtile s2*4 + q]
    #pragma unroll
    for (int j = 0; j < 8; ++j)
        #pragma unroll
        for (int q = 0; q < 8; ++q) acc[j][q] = 0.f;

    for (int c = 0; c < nch; ++c) {
        int kw = c * 8;
        const float* ab;
        int kd, poff;
        if (is_shape) {
            if (c < 5) { ab = idBase; kd = 80; poff = 0; }
            else       { ab = exBase; kd = 64; poff = 40; }
        } else       { ab = texBase; kd = 80; poff = 0; }
        int p0 = kw + tig - poff;
        // subtile 0: rows[0], rows[1]; subtile 1: rows[2], rows[3]
        uint2 a00 = load_split(ab, kd, lrows[0], p0);
        uint2 a01 = load_split(ab, kd, lrows[1], p0);
        uint2 a02 = load_split(ab, kd, lrows[0], p0 + 4);
        uint2 a03 = load_split(ab, kd, lrows[1], p0 + 4);
        uint2 a10 = load_split(ab, kd, lrows[2], p0);
        uint2 a11 = load_split(ab, kd, lrows[3], p0);
        uint2 a12 = load_split(ab, kd, lrows[2], p0 + 4);
        uint2 a13 = load_split(ab, kd, lrows[3], p0 + 4);

        const uint2* bbase = g_Bpk + (size_t)(n0 + g) * 112 + kboff + kw + 2 * tig;
        #pragma unroll
        for (int j = 0; j < 8; ++j) {
            uint4 bv = *reinterpret_cast<const uint4*>(bbase + (size_t)j * 8 * 112);
            // bv = {hi_w, lo_w, hi_w4, lo_w4}
            mma_bf16(&acc[j][0], a00.x, a01.x, a02.x, a03.x, bv.x, bv.z);
            mma_bf16(&acc[j][0], a00.x, a01.x, a02.x, a03.x, bv.y, bv.w);
            mma_bf16(&acc[j][0], a00.y, a01.y, a02.y, a03.y, bv.x, bv.z);
            mma_bf16(&acc[j][4], a10.x, a11.x, a12.x, a13.x, bv.x, bv.z);
            mma_bf16(&acc[j][4], a10.x, a11.x, a12.x, a13.x, bv.y, bv.w);
            mma_bf16(&acc[j][4], a10.y, a11.y, a12.y, a13.y, bv.x, bv.z);
        }
    }

    // ---- epilogue ----
    float addv[4];
    float* dst;
    if (is_shape) {
        #pragma unroll
        for (int s = 0; s < 4; ++s)
            addv[s] = (rows[s] < NR_) ? meanshape[rows[s]] - g_mean[rows[s] % 3] : 0.f;
        dst = g_face_shape;
    } else {
        #pragma unroll
        for (int s = 0; s < 4; ++s)
            addv[s] = (rows[s] < NR_) ? meantex[rows[s]] : 0.f;
        dst = g_tex;
    }
    #pragma unroll
    for (int j = 0; j < 8; ++j) {
        int col = n0 + j * 8 + 2 * tig;
        #pragma unroll
        for (int s = 0; s < 4; ++s) {
            if (rows[s] < NR_) {
                int base = (s >> 1) * 4 + (s & 1) * 2;  // s0->0, s1->2, s2->4, s3->6
                *reinterpret_cast<float2*>(dst + (size_t)rows[s] * B_ + col) =
                    make_float2(acc[j][base] + addv[s], acc[j][base + 1] + addv[s]);
            }
        }
    }
}

// ============================================================
// gather-phase device blocks
// ============================================================
__device__ __forceinline__ void proj_block(
    int bx, const float* __restrict__ coeff, float* __restrict__ dout, float* sm)
{
    float* s    = sm;          // [96][33]
    float* srot = sm + 3200;   // [32][12]
    int t = threadIdx.x;
    int g = bx % 8;
    int v0 = (bx / 8) * 32;
    int r0 = v0 * 3;

    for (int idx = t; idx < 32 * 12; idx += 256) {
        int b_l = idx / 12, k = idx % 12;
        int b = g * 32 + b_l;
        srot[b_l * 12 + k] = (k < 9) ? g_rot[b * 9 + k] : coeff[b * CST + 254 + (k - 9)];
    }
    #pragma unroll
    for (int it = 0; it < 12; it++) {
        int idx = t + it * 256;
        int row = idx >> 5, b_l = idx & 31;
        s[row * 33 + b_l] = (r0 + row < NR_) ?
            g_face_shape[(size_t)(r0 + row) * B_ + g * 32 + b_l] : 0.f;
    }
    __syncthreads();

    int b_l = t >> 3, j = t & 7;
    int b = g * 32 + b_l;
    float m0 = srot[b_l * 12 + 0], m1 = srot[b_l * 12 + 1], m2 = srot[b_l * 12 + 2];
    float m3 = srot[b_l * 12 + 3], m4 = srot[b_l * 12 + 4], m5 = srot[b_l * 12 + 5];
    float m6 = srot[b_l * 12 + 6], m7 = srot[b_l * 12 + 7], m8 = srot[b_l * 12 + 8];
    float tx = srot[b_l * 12 + 9], ty = srot[b_l * 12 + 10], tz = srot[b_l * 12 + 11];
    #pragma unroll
    for (int w = 0; w < 4; w++) {
        int v_l = j * 4 + w;
        int v = v0 + v_l;
        if (v < NV_) {
            float x = s[(v_l * 3 + 0) * 33 + b_l];
            float y = s[(v_l * 3 + 1) * 33 + b_l];
            float z = s[(v_l * 3 + 2) * 33 + b_l];
            float* o = dout + (size_t)b * NR_ + (size_t)v * 3;
            o[0] = fmaf(m0, x, fmaf(m1, y, fmaf(m2, z, tx)));
            o[1] = fmaf(m3, x, fmaf(m4, y, fmaf(m5, z, ty)));
            o[2] = fmaf(m6, x, fmaf(m7, y, fmaf(m8, z, tz)));
        }
    }
}

__device__ __forceinline__ void fn_block(int bx, int g)
{
    int t = threadIdx.x;
    int quad = bx * 8 + (t >> 5);
    int b = g * 32 + (t & 31);
    #pragma unroll
    for (int u = 0; u < 4; u++) {
        int fid = quad * 4 + u;
        if (fid > NF_) continue;
        float* fn = g_face_norm + (size_t)(fid * 3) * B_ + b;
        if (fid == NF_) {
            fn[0] = 0.f; fn[B_] = 0.f; fn[2 * B_] = 0.f;
            continue;
        }
        int i0 = g_tri[fid * 3 + 0], i1 = g_tri[fid * 3 + 1], i2 = g_tri[fid * 3 + 2];
        const float* fs = g_face_shape;
        size_t o0 = (size_t)(3 * i0) * B_ + b;
        size_t o1 = (size_t)(3 * i1) * B_ + b;
        size_t o2 = (size_t)(3 * i2) * B_ + b;
        float v1x = fs[o0], v1y = fs[o0 + B_], v1z = fs[o0 + 2 * B_];
        float v2x = fs[o1], v2y = fs[o1 + B_], v2z = fs[o1 + 2 * B_];
        float v3x = fs[o2], v3y = fs[o2 + B_], v3z = fs[o2 + 2 * B_];
        float e1x = v1x - v2x, e1y = v1y - v2y, e1z = v1z - v2z;
        float e2x = v2x - v3x, e2y = v2y - v3y, e2z = v2z - v3z;
        fn[0]      = e1y * e2z - e1z * e2y;
        fn[B_]     = e1z * e2x - e1x * e2z;
        fn[2 * B_] = e1x * e2y - e1y * e2x;
    }
}

__device__ __forceinline__ void color_block(
    int bx, int g, const float* __restrict__ coeff,
    float* __restrict__ dout, float* sm)
{
    const float A0C0   = 0.88622692545275801f;
    const float A1C1   = 1.77245385090551603f;
    const float A2C2   = 2.42703222385900050f;
    const float A2C2D0 = 0.70062326950125306f;
    const float A2C2H  = 1.21351611192950025f;

    float* sc = sm;          // [96][33]
    float* sg = sm + 3200;   // [32][27]
    int t = threadIdx.x;
    int v0 = bx * 32;

    for (int idx = t; idx < 32 * 27; idx += 256) {
        int b_l = idx / 27, kk = idx % 27;
        int k = kk / 3, c = kk % 3;
        float gv = coeff[(size_t)(g * 32 + b_l) * CST + 227 + c * 9 + k];
        if (k == 0) gv += 0.8f;
        sg[b_l * 27 + k * 3 + c] = gv;
    }
    __syncthreads();

    int vslot = t >> 5, b_l = t & 31;
    int b = g * 32 + b_l;
    #pragma unroll
    for (int it = 0; it < 4; it++) {
        int v_l = vslot + it * 8;
        int v = v0 + v_l;
        if (v < NV_) {
            const int4* pb4 = reinterpret_cast<const int4*>(g_pbuf + v * 8);
            int4 pa = pb4[0], pbv = pb4[1];
            int f[8] = {pa.x, pa.y, pa.z, pa.w, pbv.x, pbv.y, pbv.z, pbv.w};
            float sx = 0.f, sy = 0.f, sz = 0.f;
            #pragma unroll
            for (int i = 0; i < 8; i++) {
                const float* fn = g_face_norm + (size_t)(f[i] * 3) * B_ + b;
                sx += fn[0]; sy += fn[B_]; sz += fn[2 * B_];
            }
            float inv = rsqrtf(sx * sx + sy * sy + sz * sz);
            float nx = sx * inv, ny = sy * inv, nz = sz * inv;

            float Y[9];
            Y[0] = A0C0;
            Y[1] = -A1C1 * ny;
            Y[2] =  A1C1 * nz;
            Y[3] = -A1C1 * nx;
            Y[4] =  A2C2 * nx * ny;
            Y[5] = -A2C2 * ny * nz;
            Y[6] =  A2C2D0 * (3.f * nz * nz - 1.f);
            Y[7] = -A2C2 * nx * nz;
            Y[8] =  A2C2H * (nx * nx - ny * ny);

            const float* tx = g_tex + (size_t)(v * 3) * B_ + b;
            #pragma unroll
            for (int c = 0; c < 3; c++) {
                float l = 0.f;
                #pragma unroll
                for (int k = 0; k < 9; k++) l = fmaf(Y[k], sg[b_l * 27 + k * 3 + c], l);
                float col = tx[(size_t)c * B_] * l * (1.f / 255.f);
                sc[(v_l * 3 + c) * 33 + b_l] = fminf(fmaxf(col, 0.f), 1.f);
            }
        }
    }
    __syncthreads();

    int b_l2 = t >> 3, j = t & 7;
    int b2 = g * 32 + b_l2;
    #pragma unroll
    for (int w = 0; w < 4; w++) {
        int v_l = j * 4 + w;
        int v = v0 + v_l;
        if (v < NV_) {
            float* o = dout + OUT_COLOR + (size_t)b2 * NR_ + (size_t)v * 3;
            o[0] = sc[(v_l * 3 + 0) * 33 + b_l2];
            o[1] = sc[(v_l * 3 + 1) * 33 + b_l2];
            o[2] = sc[(v_l * 3 + 2) * 33 + b_l2];
        }
    }
}

// ============================================================
__global__ void k_mix1(const float* __restrict__ coeff, float* __restrict__ dout)
{
    __shared__ __align__(16) float sm[3584];
    int bx = blockIdx.x;
    if (bx < NPROJ) {
        proj_block(bx, coeff, dout, sm);
    } else {
        fn_block(bx - NPROJ, 0);
    }
}

__global__ void k_stage(int g, const float* __restrict__ coeff,
                        float* __restrict__ dout)
{
    __shared__ __align__(16) float sm[4096];
    int bx = blockIdx.x;
    if (bx < NCOL) {
        color_block(bx, g, coeff, dout, sm);
    } else {
        fn_block(bx - NCOL, g + 1);
    }
}

// ============================================================
__global__ void k_tail(float* __restrict__ dout)
{
    int i = blockIdx.x * 256 + threadIdx.x;
    const int LM_N = B_ * NK_ * 3;
    if (i < LM_N) {
        int d = i % 3, r = i / 3;
        int k = r % NK_, b = r / NK_;
        int v = g_kp[k];
        dout[OUT_LM + i] = dout[(size_t)b * NR_ + (size_t)v * 3 + d];
    } else {
        int q = i - LM_N;
        if (q < NF_ * 3) dout[OUT_TRI + q] = (float)g_tri[q];
    }
}

// ============================================================
extern "C" void kernel_launch(void* const* d_in, const int* in_sizes, int n_in,
                              void* d_out, int out_size)
{
    (void)in_sizes; (void)n_in; (void)out_size;
    const float* coeff     = (const float*)d_in[0];
    const float* meanshape = (const float*)d_in[1];
    const float* idBase    = (const float*)d_in[2];
    const float* exBase    = (const float*)d_in[3];
    const float* meantex   = (const float*)d_in[4];
    const float* texBase   = (const float*)d_in[5];
    const void*  tri       = d_in[6];
    const void*  pbuf      = d_in[7];
    const void*  kp        = d_in[8];
    float* dout = (float*)d_out;

    k_idx    <<<128, 256>>>(tri, pbuf, kp);
    k_prep   <<<1, 256>>>(coeff, meanshape);
    k_coeffB <<<256, 112>>>(coeff);
    k_hmma   <<<2 * NT64, 256>>>(idBase, exBase, texBase, meanshape, meantex);
    k_mix1   <<<NPROJ + NFN, 256>>>(coeff, dout);
    for (int g = 0; g < 7; g++)
        k_stage<<<NCOL + NFN, 256>>>(g, coeff, dout);
    k_stage<<<NCOL, 256>>>(7, coeff, dout);
    k_tail<<<(B_ * NK_ * 3 + NF_ * 3 + 255) / 256, 256>>>(dout);
}